// round 6
// baseline (speedup 1.0000x reference)
#include <cuda_runtime.h>
#include <cstdint>

#define Nn 50000
#define Dd 128
#define Ee 800000
#define EPS_LN 1e-5f
#define SQRT_D 11.313708498984761f
#define NBLK 196  // ceil(Nn/256)

// Scratch (static device globals — allocation-free per harness rules)
__device__ float g_x[Nn * Dd];    // 25.6 MB
__device__ float g_agg[Nn * Dd];  // 25.6 MB
__device__ int   g_deg[Nn];
__device__ int   g_rp[Nn + 1];
__device__ int   g_cur[Nn];
__device__ int   g_col[Ee];
__device__ int   g_part[NBLK];
__device__ int   g_boff[NBLK];

// ---------------- packed f32x2 helpers (sm_103) -----------------------------
__device__ __forceinline__ void fma2(unsigned long long& d,
                                     unsigned long long a,
                                     unsigned long long b) {
    asm("fma.rn.f32x2 %0, %1, %2, %0;" : "+l"(d) : "l"(a), "l"(b));
}
__device__ __forceinline__ void unpack2(unsigned long long v, float& lo, float& hi) {
    asm("mov.b64 {%0, %1}, %2;" : "=f"(lo), "=f"(hi) : "l"(v));
}

// ---------------------------------------------------------------------------
// Kernel 1: x = LayerNorm(node_emb * sqrt(D) + pos_table[pos])
// ---------------------------------------------------------------------------
__global__ void embed_ln_kernel(const float* __restrict__ ne,
                                const int* __restrict__ pos,
                                const float* __restrict__ ptab,
                                const float* __restrict__ g,
                                const float* __restrict__ b) {
    int w    = (blockIdx.x * blockDim.x + threadIdx.x) >> 5;
    int lane = threadIdx.x & 31;
    if (w >= Nn) return;
    int p = pos[w];
    float4 nv = *(const float4*)(ne   + (size_t)w * Dd + lane * 4);
    float4 pv = *(const float4*)(ptab + (size_t)p * Dd + lane * 4);
    float v0 = fmaf(nv.x, SQRT_D, pv.x);
    float v1 = fmaf(nv.y, SQRT_D, pv.y);
    float v2 = fmaf(nv.z, SQRT_D, pv.z);
    float v3 = fmaf(nv.w, SQRT_D, pv.w);
    float s = v0 + v1 + v2 + v3;
    float q = v0 * v0 + v1 * v1 + v2 * v2 + v3 * v3;
#pragma unroll
    for (int m = 1; m < 32; m <<= 1) {
        s += __shfl_xor_sync(0xffffffffu, s, m);
        q += __shfl_xor_sync(0xffffffffu, q, m);
    }
    float mean = s * (1.0f / 128.0f);
    float rstd = rsqrtf(q * (1.0f / 128.0f) - mean * mean + EPS_LN);
    float4 gv = *(const float4*)(g + lane * 4);
    float4 bv = *(const float4*)(b + lane * 4);
    float4 o;
    o.x = (v0 - mean) * rstd * gv.x + bv.x;
    o.y = (v1 - mean) * rstd * gv.y + bv.y;
    o.z = (v2 - mean) * rstd * gv.z + bv.z;
    o.w = (v3 - mean) * rstd * gv.w + bv.w;
    *(float4*)(g_x + (size_t)w * Dd + lane * 4) = o;
}

// ---------------------------------------------------------------------------
// CSR build: deg histogram -> 3-stage exclusive scan -> column fill
// ---------------------------------------------------------------------------
__global__ void zero_deg_kernel() {
    int i = blockIdx.x * blockDim.x + threadIdx.x;
    if (i < Nn) g_deg[i] = 0;
}

__global__ void hist_kernel(const int* __restrict__ edge) {
    int e = blockIdx.x * blockDim.x + threadIdx.x;
    if (e < Ee) atomicAdd(&g_deg[edge[Ee + e]], 1);
}

__global__ void deg_partials_kernel() {
    __shared__ int sm[256];
    int t = threadIdx.x;
    int i = blockIdx.x * 256 + t;
    int v = (i < Nn) ? g_deg[i] : 0;
    sm[t] = v;
    __syncthreads();
#pragma unroll
    for (int o = 128; o > 0; o >>= 1) {
        if (t < o) sm[t] += sm[t + o];
        __syncthreads();
    }
    if (t == 0) g_part[blockIdx.x] = sm[0];
}

__global__ void scan_partials_kernel() {
    __shared__ int ts[256];
    int t = threadIdx.x;
    int v = (t < NBLK) ? g_part[t] : 0;
    ts[t] = v;
    __syncthreads();
#pragma unroll
    for (int off = 1; off < 256; off <<= 1) {
        int u = (t >= off) ? ts[t - off] : 0;
        __syncthreads();
        ts[t] += u;
        __syncthreads();
    }
    if (t < NBLK) g_boff[t] = ts[t] - v;  // exclusive
}

__global__ void block_scan_kernel() {
    __shared__ int ts[256];
    int t = threadIdx.x;
    int i = blockIdx.x * 256 + t;
    int v = (i < Nn) ? g_deg[i] : 0;
    ts[t] = v;
    __syncthreads();
#pragma unroll
    for (int off = 1; off < 256; off <<= 1) {
        int u = (t >= off) ? ts[t - off] : 0;
        __syncthreads();
        ts[t] += u;
        __syncthreads();
    }
    if (i < Nn) {
        int excl = ts[t] - v + g_boff[blockIdx.x];
        g_rp[i]  = excl;
        g_cur[i] = excl;
    }
    if (i == 0) g_rp[Nn] = Ee;
}

__global__ void fill_csr_kernel(const int* __restrict__ edge) {
    int e = blockIdx.x * blockDim.x + threadIdx.x;
    if (e < Ee) {
        int src = edge[e];
        int dst = edge[Ee + e];
        int p = atomicAdd(&g_cur[dst], 1);
        g_col[p] = src;
    }
}

// ---------------------------------------------------------------------------
// Aggregate: agg[i] = sum_{j in CSR row i} x[col[j]]   (one warp per row)
// ---------------------------------------------------------------------------
__global__ void aggregate_kernel() {
    int w    = (blockIdx.x * blockDim.x + threadIdx.x) >> 5;
    int lane = threadIdx.x & 31;
    if (w >= Nn) return;
    int beg = g_rp[w];
    int end = g_rp[w + 1];
    float4 a0 = make_float4(0.f, 0.f, 0.f, 0.f);
    float4 a1 = make_float4(0.f, 0.f, 0.f, 0.f);
    int jb = beg;
    while (jb < end) {
        int take = min(32, end - jb);
        int myc = (lane < take) ? __ldg(&g_col[jb + lane]) : 0;
        int u = 0;
        for (; u + 1 < take; u += 2) {
            int s0 = __shfl_sync(0xffffffffu, myc, u);
            int s1 = __shfl_sync(0xffffffffu, myc, u + 1);
            float4 v0 = *(const float4*)(g_x + (size_t)s0 * Dd + lane * 4);
            float4 v1 = *(const float4*)(g_x + (size_t)s1 * Dd + lane * 4);
            a0.x += v0.x; a0.y += v0.y; a0.z += v0.z; a0.w += v0.w;
            a1.x += v1.x; a1.y += v1.y; a1.z += v1.z; a1.w += v1.w;
        }
        if (u < take) {
            int s0 = __shfl_sync(0xffffffffu, myc, u);
            float4 v0 = *(const float4*)(g_x + (size_t)s0 * Dd + lane * 4);
            a0.x += v0.x; a0.y += v0.y; a0.z += v0.z; a0.w += v0.w;
        }
        jb += take;
    }
    float4 o;
    o.x = a0.x + a1.x; o.y = a0.y + a1.y; o.z = a0.z + a1.z; o.w = a0.w + a1.w;
    *(float4*)(g_agg + (size_t)w * Dd + lane * 4) = o;
}

// ---------------------------------------------------------------------------
// Fused dual-GEMM + bias + ReLU + residual + LayerNorm (packed f32x2 FMA)
//   h = relu(agg @ Wl + bl + x @ Wr); x_new = LN(h + x)
// 128x128 block tile, 256 threads, 8x8 thread tile, K=256 in 32 chunks of 8.
// A staged in smem PRE-DUPLICATED (each value twice) so the per-k broadcast
// operand pairs load directly via LDS.128 — no mov.b64 packs in the hot loop.
// acc held as 8x4 packed f32x2 (column pairs).
// ---------------------------------------------------------------------------
#define ASTRIDE 260   // floats per k-row of duplicated A (256 data + 4 pad)

__global__ void __launch_bounds__(256, 2)
gemm_ln_kernel(const float* __restrict__ Wl, const float* __restrict__ bl,
               const float* __restrict__ Wr, const float* __restrict__ lng,
               const float* __restrict__ lnb, float* __restrict__ dout,
               int writeOut) {
    __shared__ float As[2][8 * ASTRIDE];   // duplicated: [k][2*row+{0,1}]
    __shared__ float Bs[2][8 * 128];

    const int t    = threadIdx.x;
    const int tc   = t & 15;
    const int tr   = t >> 4;
    const int row0 = blockIdx.x * 128;

    // global-load assignments
    const int rA   = t >> 1;            // 0..127
    const int kA   = (t & 1) * 4;       // 0 or 4
    const int rowA = row0 + rA;
    const int rB   = t >> 5;            // 0..7
    const int cB   = (t & 31) * 4;      // 0..124

    unsigned long long acc2[8][4];
#pragma unroll
    for (int i = 0; i < 8; ++i)
#pragma unroll
        for (int j = 0; j < 4; ++j) acc2[i][j] = 0ull;

    float4 pa, pb;
    auto gload = [&](int ch) {
        int k0 = ch * 8;
        const float* A = (ch < 16) ? g_agg : g_x;
        const float* W = (ch < 16) ? Wl : Wr;
        int ka = k0 & 127;
        if (rowA < Nn) pa = *(const float4*)(A + (size_t)rowA * Dd + ka + kA);
        else           pa = make_float4(0.f, 0.f, 0.f, 0.f);
        pb = *(const float4*)(W + (size_t)(ka + rB) * Dd + cB);
    };
    auto sstore = [&](int buf) {
        float* ab = &As[buf][0];
        *(float2*)(ab + (kA + 0) * ASTRIDE + 2 * rA) = make_float2(pa.x, pa.x);
        *(float2*)(ab + (kA + 1) * ASTRIDE + 2 * rA) = make_float2(pa.y, pa.y);
        *(float2*)(ab + (kA + 2) * ASTRIDE + 2 * rA) = make_float2(pa.z, pa.z);
        *(float2*)(ab + (kA + 3) * ASTRIDE + 2 * rA) = make_float2(pa.w, pa.w);
        *(float4*)(&Bs[buf][rB * 128 + cB]) = pb;
    };

    gload(0);
    sstore(0);
    __syncthreads();

    for (int ch = 0; ch < 32; ++ch) {
        int cur = ch & 1;
        if (ch < 31) gload(ch + 1);
#pragma unroll
        for (int kl = 0; kl < 8; ++kl) {
            // A broadcast pairs: 8 rows duplicated = 4 x LDS.128
            const ulonglong2* ap =
                (const ulonglong2*)(&As[cur][kl * ASTRIDE + tr * 16]);
            ulonglong2 a01 = ap[0];
            ulonglong2 a23 = ap[1];
            ulonglong2 a45 = ap[2];
            ulonglong2 a67 = ap[3];
            // B column pairs: 2 x LDS.128
            const ulonglong2* bp0 =
                (const ulonglong2*)(&Bs[cur][kl * 128 + tc * 4]);
            const ulonglong2* bp1 =
                (const ulonglong2*)(&Bs[cur][kl * 128 + tc * 4 + 64]);
            ulonglong2 b01 = bp0[0];
            ulonglong2 b23 = bp1[0];
            unsigned long long av2[8] = {a01.x, a01.y, a23.x, a23.y,
                                         a45.x, a45.y, a67.x, a67.y};
            unsigned long long bv2[4] = {b01.x, b01.y, b23.x, b23.y};
#pragma unroll
            for (int i = 0; i < 8; ++i)
#pragma unroll
                for (int j = 0; j < 4; ++j)
                    fma2(acc2[i][j], av2[i], bv2[j]);
        }
        if (ch < 31) sstore((ch + 1) & 1);
        __syncthreads();
    }

    // --------------------- Epilogue: bias + relu + residual + LN -----------
    const int c0 = tc * 4;        // cols c0..c0+3
    const int c1 = 64 + tc * 4;   // cols c1..c1+3
    float bb[8], gg[8], bt[8];
    {
        float4 u0 = *(const float4*)(bl + c0);
        float4 u1 = *(const float4*)(bl + c1);
        bb[0]=u0.x; bb[1]=u0.y; bb[2]=u0.z; bb[3]=u0.w;
        bb[4]=u1.x; bb[5]=u1.y; bb[6]=u1.z; bb[7]=u1.w;
        float4 g0 = *(const float4*)(lng + c0);
        float4 g1 = *(const float4*)(lng + c1);
        gg[0]=g0.x; gg[1]=g0.y; gg[2]=g0.z; gg[3]=g0.w;
        gg[4]=g1.x; gg[5]=g1.y; gg[6]=g1.z; gg[7]=g1.w;
        float4 t0 = *(const float4*)(lnb + c0);
        float4 t1 = *(const float4*)(lnb + c1);
        bt[0]=t0.x; bt[1]=t0.y; bt[2]=t0.z; bt[3]=t0.w;
        bt[4]=t1.x; bt[5]=t1.y; bt[6]=t1.z; bt[7]=t1.w;
    }
    float* outp = writeOut ? dout : g_x;

#pragma unroll
    for (int i = 0; i < 8; ++i) {
        int r = row0 + tr * 8 + i;
        float hv[8];
        unpack2(acc2[i][0], hv[0], hv[1]);
        unpack2(acc2[i][1], hv[2], hv[3]);
        unpack2(acc2[i][2], hv[4], hv[5]);
        unpack2(acc2[i][3], hv[6], hv[7]);
        float xo[8];
        if (r < Nn) {
            float4 x0 = *(const float4*)(g_x + (size_t)r * Dd + c0);
            float4 x1 = *(const float4*)(g_x + (size_t)r * Dd + c1);
            xo[0]=x0.x; xo[1]=x0.y; xo[2]=x0.z; xo[3]=x0.w;
            xo[4]=x1.x; xo[5]=x1.y; xo[6]=x1.z; xo[7]=x1.w;
        } else {
#pragma unroll
            for (int j = 0; j < 8; ++j) xo[j] = 0.f;
        }
        float s = 0.f, q = 0.f;
#pragma unroll
        for (int j = 0; j < 8; ++j) {
            float h = hv[j] + bb[j];
            h = fmaxf(h, 0.f);
            h += xo[j];
            hv[j] = h;
            s += h;
            q += h * h;
        }
#pragma unroll
        for (int m = 1; m < 16; m <<= 1) {
            s += __shfl_xor_sync(0xffffffffu, s, m);
            q += __shfl_xor_sync(0xffffffffu, q, m);
        }
        float mean = s * (1.0f / 128.0f);
        float rstd = rsqrtf(q * (1.0f / 128.0f) - mean * mean + EPS_LN);
        if (r < Nn) {
            float4 o0, o1;
            o0.x = (hv[0] - mean) * rstd * gg[0] + bt[0];
            o0.y = (hv[1] - mean) * rstd * gg[1] + bt[1];
            o0.z = (hv[2] - mean) * rstd * gg[2] + bt[2];
            o0.w = (hv[3] - mean) * rstd * gg[3] + bt[3];
            o1.x = (hv[4] - mean) * rstd * gg[4] + bt[4];
            o1.y = (hv[5] - mean) * rstd * gg[5] + bt[5];
            o1.z = (hv[6] - mean) * rstd * gg[6] + bt[6];
            o1.w = (hv[7] - mean) * rstd * gg[7] + bt[7];
            *(float4*)(outp + (size_t)r * Dd + c0) = o0;
            *(float4*)(outp + (size_t)r * Dd + c1) = o1;
        }
    }
}

// ---------------------------------------------------------------------------
extern "C" void kernel_launch(void* const* d_in, const int* in_sizes, int n_in,
                              void* d_out, int out_size) {
    const float* node_emb  = (const float*)d_in[0];
    const int*   pos       = (const int*)d_in[1];
    const int*   edge      = (const int*)d_in[2];
    const float* pos_table = (const float*)d_in[3];
    const float* Wl        = (const float*)d_in[4];
    const float* bl        = (const float*)d_in[5];
    const float* Wr        = (const float*)d_in[6];
    const float* emb_g     = (const float*)d_in[7];
    const float* emb_b     = (const float*)d_in[8];
    const float* hid_g     = (const float*)d_in[9];
    const float* hid_b     = (const float*)d_in[10];
    float* out = (float*)d_out;

    // embedding + LN
    embed_ln_kernel<<<(Nn * 32 + 255) / 256, 256>>>(node_emb, pos, pos_table,
                                                    emb_g, emb_b);
    // CSR build (reused by all 3 layers)
    zero_deg_kernel<<<NBLK, 256>>>();
    hist_kernel<<<(Ee + 255) / 256, 256>>>(edge);
    deg_partials_kernel<<<NBLK, 256>>>();
    scan_partials_kernel<<<1, 256>>>();
    block_scan_kernel<<<NBLK, 256>>>();
    fill_csr_kernel<<<(Ee + 255) / 256, 256>>>(edge);

    const int gemm_blocks = (Nn + 127) / 128;  // 391
    for (int l = 0; l < 3; ++l) {
        aggregate_kernel<<<(Nn * 32 + 255) / 256, 256>>>();
        gemm_ln_kernel<<<gemm_blocks, 256>>>(Wl + (size_t)l * Dd * Dd,
                                             bl + (size_t)l * Dd,
                                             Wr + (size_t)l * Dd * Dd,
                                             hid_g + (size_t)l * Dd,
                                             hid_b + (size_t)l * Dd,
                                             out, l == 2 ? 1 : 0);
    }
}

// round 8
// speedup vs baseline: 1.4655x; 1.4655x over previous
#include <cuda_runtime.h>
#include <cuda_fp16.h>
#include <cstdint>

#define Nn 50000
#define Dd 128
#define Ee 800000
#define EPS_LN 1e-5f
#define SQRT_D 11.313708498984761f
#define NBLK 196  // ceil(Nn/256)

// Scratch (static device globals — allocation-free per harness rules)
__device__ float  g_x[Nn * Dd];      // fp32 features (residual + gather source)
__device__ __half g_xh[Nn * Dd];     // fp16 hi split of x
__device__ __half g_xl[Nn * Dd];     // fp16 lo split of x
__device__ __half g_aggh[Nn * Dd];   // fp16 hi split of agg
__device__ __half g_aggl[Nn * Dd];   // fp16 lo split of agg
__device__ __half g_bth[3 * 128 * 256];  // W^T hi, [layer][n][k] (k<128:Wl, else Wr)
__device__ __half g_btl[3 * 128 * 256];  // W^T lo
__device__ int    g_deg[Nn];
__device__ int    g_rp[Nn + 1];
__device__ int    g_cur[Nn];
__device__ int    g_col[Ee];
__device__ int    g_part[NBLK];
__device__ int    g_boff[NBLK];

// ======================= PTX helpers ========================================
__device__ __forceinline__ uint32_t smem_u32(const void* p) {
    uint32_t a;
    asm("{ .reg .u64 t; cvta.to.shared.u64 t, %1; cvt.u32.u64 %0, t; }"
        : "=r"(a) : "l"(p));
    return a;
}
__device__ __forceinline__ void cp16(uint32_t dst, const void* src, int valid) {
    asm volatile("cp.async.ca.shared.global [%0], [%1], 16, %2;"
                 :: "r"(dst),
                    "l"((unsigned long long)__cvta_generic_to_global(src)),
                    "r"(valid ? 16 : 0));
}
#define CP_COMMIT() asm volatile("cp.async.commit_group;" ::: "memory")
#define CP_WAIT0()  asm volatile("cp.async.wait_group 0;" ::: "memory")

__device__ __forceinline__ void ldsm4(uint32_t* r, uint32_t addr) {
    asm volatile("ldmatrix.sync.aligned.m8n8.x4.shared.b16 {%0,%1,%2,%3}, [%4];"
                 : "=r"(r[0]), "=r"(r[1]), "=r"(r[2]), "=r"(r[3]) : "r"(addr));
}
__device__ __forceinline__ void mma16816(float* d, const uint32_t* a,
                                         const uint32_t* b) {
    asm volatile(
        "mma.sync.aligned.m16n8k16.row.col.f32.f16.f16.f32 "
        "{%0,%1,%2,%3}, {%4,%5,%6,%7}, {%8,%9}, {%0,%1,%2,%3};"
        : "+f"(d[0]), "+f"(d[1]), "+f"(d[2]), "+f"(d[3])
        : "r"(a[0]), "r"(a[1]), "r"(a[2]), "r"(a[3]), "r"(b[0]), "r"(b[1]));
}
__device__ __forceinline__ void split_h(float v, __half& hi, __half& lo) {
    hi = __float2half_rn(v);
    lo = __float2half_rn(v - __half2float(hi));
}

// ---------------------------------------------------------------------------
// Kernel 1: x = LayerNorm(node_emb * sqrt(D) + pos_table[pos]); emit hi/lo.
// ---------------------------------------------------------------------------
__global__ void embed_ln_kernel(const float* __restrict__ ne,
                                const int* __restrict__ pos,
                                const float* __restrict__ ptab,
                                const float* __restrict__ g,
                                const float* __restrict__ b) {
    int w    = (blockIdx.x * blockDim.x + threadIdx.x) >> 5;
    int lane = threadIdx.x & 31;
    if (w >= Nn) return;
    int p = pos[w];
    float4 nv = *(const float4*)(ne   + (size_t)w * Dd + lane * 4);
    float4 pv = *(const float4*)(ptab + (size_t)p * Dd + lane * 4);
    float v0 = fmaf(nv.x, SQRT_D, pv.x);
    float v1 = fmaf(nv.y, SQRT_D, pv.y);
    float v2 = fmaf(nv.z, SQRT_D, pv.z);
    float v3 = fmaf(nv.w, SQRT_D, pv.w);
    float s = v0 + v1 + v2 + v3;
    float q = v0 * v0 + v1 * v1 + v2 * v2 + v3 * v3;
#pragma unroll
    for (int m = 1; m < 32; m <<= 1) {
        s += __shfl_xor_sync(0xffffffffu, s, m);
        q += __shfl_xor_sync(0xffffffffu, q, m);
    }
    float mean = s * (1.0f / 128.0f);
    float rstd = rsqrtf(q * (1.0f / 128.0f) - mean * mean + EPS_LN);
    float4 gv = *(const float4*)(g + lane * 4);
    float4 bv = *(const float4*)(b + lane * 4);
    float4 o;
    o.x = (v0 - mean) * rstd * gv.x + bv.x;
    o.y = (v1 - mean) * rstd * gv.y + bv.y;
    o.z = (v2 - mean) * rstd * gv.z + bv.z;
    o.w = (v3 - mean) * rstd * gv.w + bv.w;
    size_t off = (size_t)w * Dd + lane * 4;
    *(float4*)(g_x + off) = o;
    __half h0, l0, h1, l1, h2, l2, h3, l3;
    split_h(o.x, h0, l0); split_h(o.y, h1, l1);
    split_h(o.z, h2, l2); split_h(o.w, h3, l3);
    *(__half2*)(g_xh + off)     = __half2(h0, h1);
    *(__half2*)(g_xh + off + 2) = __half2(h2, h3);
    *(__half2*)(g_xl + off)     = __half2(l0, l1);
    *(__half2*)(g_xl + off + 2) = __half2(l2, l3);
}

// ---------------------------------------------------------------------------
// W^T hi/lo build: all 3 layers, bt[l][n][k] (k<128 -> Wl, else Wr)
// ---------------------------------------------------------------------------
__global__ void wt_kernel(const float* __restrict__ Wl,
                          const float* __restrict__ Wr) {
    int idx = blockIdx.x * blockDim.x + threadIdx.x;  // 3*128*256 = 98304
    if (idx >= 3 * 128 * 256) return;
    int l = idx >> 15;
    int r = idx & 32767;
    int n = r >> 8;
    int k = r & 255;
    float v = (k < 128) ? Wl[(size_t)l * Dd * Dd + k * Dd + n]
                        : Wr[(size_t)l * Dd * Dd + (k - 128) * Dd + n];
    __half hi, lo;
    split_h(v, hi, lo);
    g_bth[idx] = hi;
    g_btl[idx] = lo;
}

// ---------------------------------------------------------------------------
// CSR build: deg histogram -> 3-stage exclusive scan -> column fill
// ---------------------------------------------------------------------------
__global__ void zero_deg_kernel() {
    int i = blockIdx.x * blockDim.x + threadIdx.x;
    if (i < Nn) g_deg[i] = 0;
}

__global__ void hist_kernel(const int* __restrict__ edge) {
    int e = blockIdx.x * blockDim.x + threadIdx.x;
    if (e < Ee) atomicAdd(&g_deg[edge[Ee + e]], 1);
}

__global__ void deg_partials_kernel() {
    __shared__ int sm[256];
    int t = threadIdx.x;
    int i = blockIdx.x * 256 + t;
    int v = (i < Nn) ? g_deg[i] : 0;
    sm[t] = v;
    __syncthreads();
#pragma unroll
    for (int o = 128; o > 0; o >>= 1) {
        if (t < o) sm[t] += sm[t + o];
        __syncthreads();
    }
    if (t == 0) g_part[blockIdx.x] = sm[0];
}

__global__ void scan_partials_kernel() {
    __shared__ int ts[256];
    int t = threadIdx.x;
    int v = (t < NBLK) ? g_part[t] : 0;
    ts[t] = v;
    __syncthreads();
#pragma unroll
    for (int off = 1; off < 256; off <<= 1) {
        int u = (t >= off) ? ts[t - off] : 0;
        __syncthreads();
        ts[t] += u;
        __syncthreads();
    }
    if (t < NBLK) g_boff[t] = ts[t] - v;  // exclusive
}

__global__ void block_scan_kernel() {
    __shared__ int ts[256];
    int t = threadIdx.x;
    int i = blockIdx.x * 256 + t;
    int v = (i < Nn) ? g_deg[i] : 0;
    ts[t] = v;
    __syncthreads();
#pragma unroll
    for (int off = 1; off < 256; off <<= 1) {
        int u = (t >= off) ? ts[t - off] : 0;
        __syncthreads();
        ts[t] += u;
        __syncthreads();
    }
    if (i < Nn) {
        int excl = ts[t] - v + g_boff[blockIdx.x];
        g_rp[i]  = excl;
        g_cur[i] = excl;
    }
    if (i == 0) g_rp[Nn] = Ee;
}

__global__ void fill_csr_kernel(const int* __restrict__ edge) {
    int e = blockIdx.x * blockDim.x + threadIdx.x;
    if (e < Ee) {
        int src = edge[e];
        int dst = edge[Ee + e];
        int p = atomicAdd(&g_cur[dst], 1);
        g_col[p] = src;
    }
}

// ---------------------------------------------------------------------------
// Aggregate: agg[i] = sum_{j in row i} x[col[j]]; emit fp16 hi/lo only.
// ---------------------------------------------------------------------------
__global__ void aggregate_kernel() {
    int w    = (blockIdx.x * blockDim.x + threadIdx.x) >> 5;
    int lane = threadIdx.x & 31;
    if (w >= Nn) return;
    int beg = g_rp[w];
    int end = g_rp[w + 1];
    float4 a0 = make_float4(0.f, 0.f, 0.f, 0.f);
    float4 a1 = make_float4(0.f, 0.f, 0.f, 0.f);
    int jb = beg;
    while (jb < end) {
        int take = min(32, end - jb);
        int myc = (lane < take) ? __ldg(&g_col[jb + lane]) : 0;
        int u = 0;
        for (; u + 1 < take; u += 2) {
            int s0 = __shfl_sync(0xffffffffu, myc, u);
            int s1 = __shfl_sync(0xffffffffu, myc, u + 1);
            float4 v0 = *(const float4*)(g_x + (size_t)s0 * Dd + lane * 4);
            float4 v1 = *(const float4*)(g_x + (size_t)s1 * Dd + lane * 4);
            a0.x += v0.x; a0.y += v0.y; a0.z += v0.z; a0.w += v0.w;
            a1.x += v1.x; a1.y += v1.y; a1.z += v1.z; a1.w += v1.w;
        }
        if (u < take) {
            int s0 = __shfl_sync(0xffffffffu, myc, u);
            float4 v0 = *(const float4*)(g_x + (size_t)s0 * Dd + lane * 4);
            a0.x += v0.x; a0.y += v0.y; a0.z += v0.z; a0.w += v0.w;
        }
        jb += take;
    }
    float o0 = a0.x + a1.x, o1 = a0.y + a1.y;
    float o2 = a0.z + a1.z, o3 = a0.w + a1.w;
    size_t off = (size_t)w * Dd + lane * 4;
    __half h0, l0, h1, l1, h2, l2, h3, l3;
    split_h(o0, h0, l0); split_h(o1, h1, l1);
    split_h(o2, h2, l2); split_h(o3, h3, l3);
    *(__half2*)(g_aggh + off)     = __half2(h0, h1);
    *(__half2*)(g_aggh + off + 2) = __half2(h2, h3);
    *(__half2*)(g_aggl + off)     = __half2(l0, l1);
    *(__half2*)(g_aggl + off + 2) = __half2(l2, l3);
}

// ---------------------------------------------------------------------------
// mma.sync fp16-split dual-GEMM + bias + ReLU + residual + LayerNorm
//   acc = [agg|x] @ [Wl;Wr]  via 3-pass split fp16 (ah*bh + ah*bl + al*bh)
//   x_new = LN(relu(acc + bl) + x)
// CTA: 128x128 tile, 256 thr (8 warps, warp = 32x64). K=256 in 8 chunks of 32.
// smem: double-buffered {Ahi,Alo,Bhi,Blo}, rows of 40 half (conflict-free LDSM).
// NOTE: layer index passed as int; W^T hi/lo offsets computed in DEVICE code
// (device symbols must never be address-taken on the host).
// ---------------------------------------------------------------------------
#define STR_H   40
#define TILE_HB (128 * STR_H * 2)          // 10240 B per tile
#define BUF_HB  (4 * TILE_HB)              // 40960 B per buffer
#define SMEM_MMA (2 * BUF_HB)              // 81920 B

__global__ void __launch_bounds__(256)
gemm_mma_kernel(int layer,
                const float* __restrict__ bias, const float* __restrict__ lng,
                const float* __restrict__ lnb, float* __restrict__ dout,
                int writeOut) {
    extern __shared__ char smem[];
    const uint32_t su = smem_u32(smem);
    const __half* bth = g_bth + (size_t)layer * 128 * 256;
    const __half* btl = g_btl + (size_t)layer * 128 * 256;
    const int t    = threadIdx.x;
    const int wid  = t >> 5;
    const int lane = t & 31;
    const int row0 = blockIdx.x * 128;
    const int mg   = wid & 3;         // m-group: rows mg*32..+31
    const int nh   = wid >> 2;        // n-half : cols nh*64..+63
    const int n0   = nh * 64;

    // staging assignment: rows sr, sr+64; 16B segment sg
    const int sr = t >> 2;
    const int sg = t & 3;

    float acc[64];                    // [mt][nt][4]
#pragma unroll
    for (int i = 0; i < 64; ++i) acc[i] = 0.f;

    auto stage = [&](int c) {
        const uint32_t bb = su + (c & 1) * BUF_HB;
        const __half* Ah = (c < 4) ? g_aggh : g_xh;
        const __half* Al = (c < 4) ? g_aggl : g_xl;
        const int ka = (c & 3) * 32;
#pragma unroll
        for (int rr = 0; rr < 2; ++rr) {
            const int r = sr + rr * 64;
            const int grow = row0 + r;
            const int ok = (grow < Nn);
            const size_t asrc = (size_t)(ok ? grow : 0) * Dd + ka + sg * 8;
            const uint32_t dofs = (uint32_t)(r * STR_H + sg * 8) * 2;
            cp16(bb + dofs,             Ah + asrc, ok);
            cp16(bb + TILE_HB + dofs,   Al + asrc, ok);
            const size_t bsrc = (size_t)r * 256 + c * 32 + sg * 8;
            cp16(bb + 2 * TILE_HB + dofs, bth + bsrc, 1);
            cp16(bb + 3 * TILE_HB + dofs, btl + bsrc, 1);
        }
        CP_COMMIT();
    };

    // ldmatrix lane-address components
    const int aRow = mg * 32 + (lane & 15);           // + mt*16
    const int aCol = (lane >> 4) * 8;                 // + kk
    const int bRow = n0 + (lane & 7) + ((lane >> 4) << 3);  // + g*16
    const int bCol = ((lane >> 3) & 1) * 8;           // + kk

    stage(0);
    CP_WAIT0();
    __syncthreads();

    for (int c = 0; c < 8; ++c) {
        const uint32_t bb = su + (c & 1) * BUF_HB;
        if (c < 7) stage(c + 1);
#pragma unroll
        for (int kk = 0; kk < 32; kk += 16) {
            uint32_t ah[2][4], al[2][4], bh[4][4], blo[4][4];
#pragma unroll
            for (int mt = 0; mt < 2; ++mt) {
                uint32_t ao = (uint32_t)((aRow + mt * 16) * STR_H + aCol + kk) * 2;
                ldsm4(ah[mt], bb + ao);
                ldsm4(al[mt], bb + TILE_HB + ao);
            }
#pragma unroll
            for (int g = 0; g < 4; ++g) {
                uint32_t bo = (uint32_t)((bRow + g * 16) * STR_H + bCol + kk) * 2;
                ldsm4(bh[g],  bb + 2 * TILE_HB + bo);
                ldsm4(blo[g], bb + 3 * TILE_HB + bo);
            }
#pragma unroll
            for (int mt = 0; mt < 2; ++mt)
#pragma unroll
                for (int g = 0; g < 4; ++g) {
                    float* d0 = &acc[(mt * 8 + 2 * g) * 4];
                    float* d1 = &acc[(mt * 8 + 2 * g + 1) * 4];
                    mma16816(d0, ah[mt], &bh[g][0]);
                    mma16816(d1, ah[mt], &bh[g][2]);
                    mma16816(d0, ah[mt], &blo[g][0]);
                    mma16816(d1, ah[mt], &blo[g][2]);
                    mma16816(d0, al[mt], &bh[g][0]);
                    mma16816(d1, al[mt], &bh[g][2]);
                }
        }
        if (c < 7) CP_WAIT0();
        __syncthreads();
    }

    // ------------------- Epilogue: bias+relu+residual+LN -------------------
    float* sred = (float*)smem;            // [128][8]
    float* qred = (float*)(smem + 4096);   // [128][8]

#pragma unroll
    for (int mt = 0; mt < 2; ++mt) {
        const int rl = mg * 32 + mt * 16 + (lane >> 2);
        const int rh = rl + 8;
        const int gl = row0 + rl, gh = row0 + rh;
        float sl = 0.f, ql = 0.f, sh = 0.f, qh = 0.f;
#pragma unroll
        for (int nt = 0; nt < 8; ++nt) {
            const int cc = n0 + nt * 8 + (lane & 3) * 2;
            float2 bi = *(const float2*)(bias + cc);
            float* a = &acc[(mt * 8 + nt) * 4];
            float h0 = fmaxf(a[0] + bi.x, 0.f);
            float h1 = fmaxf(a[1] + bi.y, 0.f);
            float h2 = fmaxf(a[2] + bi.x, 0.f);
            float h3 = fmaxf(a[3] + bi.y, 0.f);
            float2 xl2 = (gl < Nn) ? *(const float2*)(g_x + (size_t)gl * Dd + cc)
                                   : make_float2(0.f, 0.f);
            float2 xh2 = (gh < Nn) ? *(const float2*)(g_x + (size_t)gh * Dd + cc)
                                   : make_float2(0.f, 0.f);
            h0 += xl2.x; h1 += xl2.y; h2 += xh2.x; h3 += xh2.y;
            a[0] = h0; a[1] = h1; a[2] = h2; a[3] = h3;
            sl += h0 + h1; ql += h0 * h0 + h1 * h1;
            sh += h2 + h3; qh += h2 * h2 + h3 * h3;
        }
        sred[rl * 8 + nh * 4 + (lane & 3)] = sl;
        qred[rl * 8 + nh * 4 + (lane & 3)] = ql;
        sred[rh * 8 + nh * 4 + (lane & 3)] = sh;
        qred[rh * 8 + nh * 4 + (lane & 3)] = qh;
    }
    __syncthreads();

#pragma unroll
    for (int mt = 0; mt < 2; ++mt) {
        const int rl = mg * 32 + mt * 16 + (lane >> 2);
        const int rh = rl + 8;
        const int gl = row0 + rl, gh = row0 + rh;
        float s1 = 0.f, q1 = 0.f, s2 = 0.f, q2 = 0.f;
#pragma unroll
        for (int j = 0; j < 8; ++j) {
            s1 += sred[rl * 8 + j]; q1 += qred[rl * 8 + j];
            s2 += sred[rh * 8 + j]; q2 += qred[rh * 8 + j];
        }
        float m1 = s1 * (1.0f / 128.0f);
        float r1 = rsqrtf(q1 * (1.0f / 128.0f) - m1 * m1 + EPS_LN);
        float m2 = s2 * (1.0f / 128.0f);
        float r2 = rsqrtf(q2 * (1.0f / 128.0f) - m2 * m2 + EPS_LN);
#pragma unroll
        for (int nt = 0; nt < 8; ++nt) {
            const int cc = n0 + nt * 8 + (lane & 3) * 2;
            float2 gv = *(const float2*)(lng + cc);
            float2 tv = *(const float2*)(lnb + cc);
            float* a = &acc[(mt * 8 + nt) * 4];
            if (gl < Nn) {
                float o0 = (a[0] - m1) * r1 * gv.x + tv.x;
                float o1 = (a[1] - m1) * r1 * gv.y + tv.y;
                size_t off = (size_t)gl * Dd + cc;
                if (writeOut) {
                    *(float2*)(dout + off) = make_float2(o0, o1);
                } else {
                    *(float2*)(g_x + off) = make_float2(o0, o1);
                    __half hh0, ll0, hh1, ll1;
                    split_h(o0, hh0, ll0); split_h(o1, hh1, ll1);
                    *(__half2*)(g_xh + off) = __half2(hh0, hh1);
                    *(__half2*)(g_xl + off) = __half2(ll0, ll1);
                }
            }
            if (gh < Nn) {
                float o2 = (a[2] - m2) * r2 * gv.x + tv.x;
                float o3 = (a[3] - m2) * r2 * gv.y + tv.y;
                size_t off = (size_t)gh * Dd + cc;
                if (writeOut) {
                    *(float2*)(dout + off) = make_float2(o2, o3);
                } else {
                    *(float2*)(g_x + off) = make_float2(o2, o3);
                    __half hh2, ll2, hh3, ll3;
                    split_h(o2, hh2, ll2); split_h(o3, hh3, ll3);
                    *(__half2*)(g_xh + off) = __half2(hh2, hh3);
                    *(__half2*)(g_xl + off) = __half2(ll2, ll3);
                }
            }
        }
    }
}

// ---------------------------------------------------------------------------
extern "C" void kernel_launch(void* const* d_in, const int* in_sizes, int n_in,
                              void* d_out, int out_size) {
    const float* node_emb  = (const float*)d_in[0];
    const int*   pos       = (const int*)d_in[1];
    const int*   edge      = (const int*)d_in[2];
    const float* pos_table = (const float*)d_in[3];
    const float* Wl        = (const float*)d_in[4];
    const float* bl        = (const float*)d_in[5];
    const float* Wr        = (const float*)d_in[6];
    const float* emb_g     = (const float*)d_in[7];
    const float* emb_b     = (const float*)d_in[8];
    const float* hid_g     = (const float*)d_in[9];
    const float* hid_b     = (const float*)d_in[10];
    float* out = (float*)d_out;

    cudaFuncSetAttribute(gemm_mma_kernel,
                         cudaFuncAttributeMaxDynamicSharedMemorySize, SMEM_MMA);

    // embedding + LN (+ fp16 splits)
    embed_ln_kernel<<<(Nn * 32 + 255) / 256, 256>>>(node_emb, pos, pos_table,
                                                    emb_g, emb_b);
    // W^T hi/lo for all layers
    wt_kernel<<<(3 * 128 * 256 + 255) / 256, 256>>>(Wl, Wr);
    // CSR build (reused by all 3 layers)
    zero_deg_kernel<<<NBLK, 256>>>();
    hist_kernel<<<(Ee + 255) / 256, 256>>>(edge);
    deg_partials_kernel<<<NBLK, 256>>>();
    scan_partials_kernel<<<1, 256>>>();
    block_scan_kernel<<<NBLK, 256>>>();
    fill_csr_kernel<<<(Ee + 255) / 256, 256>>>(edge);

    const int gemm_blocks = (Nn + 127) / 128;  // 391
    for (int l = 0; l < 3; ++l) {
        aggregate_kernel<<<(Nn * 32 + 255) / 256, 256>>>();
        gemm_mma_kernel<<<gemm_blocks, 256, SMEM_MMA>>>(
            l, bl + (size_t)l * Dd, hid_g + (size_t)l * Dd,
            hid_b + (size_t)l * Dd, out, l == 2 ? 1 : 0);
    }
}

// round 9
// speedup vs baseline: 1.5132x; 1.0326x over previous
#include <cuda_runtime.h>
#include <cuda_fp16.h>
#include <cstdint>

#define Nn 50000
#define Dd 128
#define Ee 800000
#define EPS_LN 1e-5f
#define SQRT_D 11.313708498984761f
#define NBLK 196  // ceil(Nn/256)

// Scratch (static device globals — allocation-free per harness rules)
__device__ __half g_xh[Nn * Dd];     // fp16 hi split of x
__device__ __half g_xl[Nn * Dd];     // fp16 lo split of x
__device__ __half g_aggh[Nn * Dd];   // fp16 hi split of agg
__device__ __half g_aggl[Nn * Dd];   // fp16 lo split of agg
__device__ __half g_bth[3 * 128 * 256];  // W^T hi, [layer][n][k] (k<128:Wl, else Wr)
__device__ __half g_btl[3 * 128 * 256];  // W^T lo
__device__ int    g_deg[Nn];
__device__ int    g_rp[Nn + 1];
__device__ int    g_cur[Nn];
__device__ int    g_col[Ee];
__device__ int    g_part[NBLK];
__device__ int    g_boff[NBLK];

// ======================= PTX helpers ========================================
__device__ __forceinline__ uint32_t smem_u32(const void* p) {
    uint32_t a;
    asm("{ .reg .u64 t; cvta.to.shared.u64 t, %1; cvt.u32.u64 %0, t; }"
        : "=r"(a) : "l"(p));
    return a;
}
__device__ __forceinline__ void cp16(uint32_t dst, const void* src, int valid) {
    asm volatile("cp.async.ca.shared.global [%0], [%1], 16, %2;"
                 :: "r"(dst),
                    "l"((unsigned long long)__cvta_generic_to_global(src)),
                    "r"(valid ? 16 : 0));
}
#define CP_COMMIT() asm volatile("cp.async.commit_group;" ::: "memory")
#define CP_WAIT0()  asm volatile("cp.async.wait_group 0;" ::: "memory")

__device__ __forceinline__ void ldsm4(uint32_t* r, uint32_t addr) {
    asm volatile("ldmatrix.sync.aligned.m8n8.x4.shared.b16 {%0,%1,%2,%3}, [%4];"
                 : "=r"(r[0]), "=r"(r[1]), "=r"(r[2]), "=r"(r[3]) : "r"(addr));
}
__device__ __forceinline__ void mma16816(float* d, const uint32_t* a,
                                         const uint32_t* b) {
    asm volatile(
        "mma.sync.aligned.m16n8k16.row.col.f32.f16.f16.f32 "
        "{%0,%1,%2,%3}, {%4,%5,%6,%7}, {%8,%9}, {%0,%1,%2,%3};"
        : "+f"(d[0]), "+f"(d[1]), "+f"(d[2]), "+f"(d[3])
        : "r"(a[0]), "r"(a[1]), "r"(a[2]), "r"(a[3]), "r"(b[0]), "r"(b[1]));
}
__device__ __forceinline__ void split_h(float v, __half& hi, __half& lo) {
    hi = __float2half_rn(v);
    lo = __float2half_rn(v - __half2float(hi));
}
// reconstruct fp32 pair from hi/lo half2 arrays at (aligned) offset
__device__ __forceinline__ float2 recon2(const __half* hp, const __half* lp,
                                         size_t off) {
    float2 fh = __half22float2(*(const __half2*)(hp + off));
    float2 fl = __half22float2(*(const __half2*)(lp + off));
    return make_float2(fh.x + fl.x, fh.y + fl.y);
}

// ---------------------------------------------------------------------------
// Kernel 1: x = LayerNorm(node_emb * sqrt(D) + pos_table[pos]); emit hi/lo.
// ---------------------------------------------------------------------------
__global__ void embed_ln_kernel(const float* __restrict__ ne,
                                const int* __restrict__ pos,
                                const float* __restrict__ ptab,
                                const float* __restrict__ g,
                                const float* __restrict__ b) {
    int w    = (blockIdx.x * blockDim.x + threadIdx.x) >> 5;
    int lane = threadIdx.x & 31;
    if (w >= Nn) return;
    int p = pos[w];
    float4 nv = *(const float4*)(ne   + (size_t)w * Dd + lane * 4);
    float4 pv = *(const float4*)(ptab + (size_t)p * Dd + lane * 4);
    float v0 = fmaf(nv.x, SQRT_D, pv.x);
    float v1 = fmaf(nv.y, SQRT_D, pv.y);
    float v2 = fmaf(nv.z, SQRT_D, pv.z);
    float v3 = fmaf(nv.w, SQRT_D, pv.w);
    float s = v0 + v1 + v2 + v3;
    float q = v0 * v0 + v1 * v1 + v2 * v2 + v3 * v3;
#pragma unroll
    for (int m = 1; m < 32; m <<= 1) {
        s += __shfl_xor_sync(0xffffffffu, s, m);
        q += __shfl_xor_sync(0xffffffffu, q, m);
    }
    float mean = s * (1.0f / 128.0f);
    float rstd = rsqrtf(q * (1.0f / 128.0f) - mean * mean + EPS_LN);
    float4 gv = *(const float4*)(g + lane * 4);
    float4 bv = *(const float4*)(b + lane * 4);
    float4 o;
    o.x = (v0 - mean) * rstd * gv.x + bv.x;
    o.y = (v1 - mean) * rstd * gv.y + bv.y;
    o.z = (v2 - mean) * rstd * gv.z + bv.z;
    o.w = (v3 - mean) * rstd * gv.w + bv.w;
    size_t off = (size_t)w * Dd + lane * 4;
    __half h0, l0, h1, l1, h2, l2, h3, l3;
    split_h(o.x, h0, l0); split_h(o.y, h1, l1);
    split_h(o.z, h2, l2); split_h(o.w, h3, l3);
    *(__half2*)(g_xh + off)     = __half2(h0, h1);
    *(__half2*)(g_xh + off + 2) = __half2(h2, h3);
    *(__half2*)(g_xl + off)     = __half2(l0, l1);
    *(__half2*)(g_xl + off + 2) = __half2(l2, l3);
}

// ---------------------------------------------------------------------------
// W^T hi/lo build: all 3 layers, bt[l][n][k] (k<128 -> Wl, else Wr)
// ---------------------------------------------------------------------------
__global__ void wt_kernel(const float* __restrict__ Wl,
                          const float* __restrict__ Wr) {
    int idx = blockIdx.x * blockDim.x + threadIdx.x;  // 3*128*256 = 98304
    if (idx >= 3 * 128 * 256) return;
    int l = idx >> 15;
    int r = idx & 32767;
    int n = r >> 8;
    int k = r & 255;
    float v = (k < 128) ? Wl[(size_t)l * Dd * Dd + k * Dd + n]
                        : Wr[(size_t)l * Dd * Dd + (k - 128) * Dd + n];
    __half hi, lo;
    split_h(v, hi, lo);
    g_bth[idx] = hi;
    g_btl[idx] = lo;
}

// ---------------------------------------------------------------------------
// CSR build: deg histogram -> 3-stage exclusive scan -> column fill
// ---------------------------------------------------------------------------
__global__ void zero_deg_kernel() {
    int i = blockIdx.x * blockDim.x + threadIdx.x;
    if (i < Nn) g_deg[i] = 0;
}

__global__ void hist_kernel(const int* __restrict__ edge) {
    int e = blockIdx.x * blockDim.x + threadIdx.x;
    if (e < Ee) atomicAdd(&g_deg[edge[Ee + e]], 1);
}

__global__ void deg_partials_kernel() {
    __shared__ int sm[256];
    int t = threadIdx.x;
    int i = blockIdx.x * 256 + t;
    int v = (i < Nn) ? g_deg[i] : 0;
    sm[t] = v;
    __syncthreads();
#pragma unroll
    for (int o = 128; o > 0; o >>= 1) {
        if (t < o) sm[t] += sm[t + o];
        __syncthreads();
    }
    if (t == 0) g_part[blockIdx.x] = sm[0];
}

__global__ void scan_partials_kernel() {
    __shared__ int ts[256];
    int t = threadIdx.x;
    int v = (t < NBLK) ? g_part[t] : 0;
    ts[t] = v;
    __syncthreads();
#pragma unroll
    for (int off = 1; off < 256; off <<= 1) {
        int u = (t >= off) ? ts[t - off] : 0;
        __syncthreads();
        ts[t] += u;
        __syncthreads();
    }
    if (t < NBLK) g_boff[t] = ts[t] - v;  // exclusive
}

__global__ void block_scan_kernel() {
    __shared__ int ts[256];
    int t = threadIdx.x;
    int i = blockIdx.x * 256 + t;
    int v = (i < Nn) ? g_deg[i] : 0;
    ts[t] = v;
    __syncthreads();
#pragma unroll
    for (int off = 1; off < 256; off <<= 1) {
        int u = (t >= off) ? ts[t - off] : 0;
        __syncthreads();
        ts[t] += u;
        __syncthreads();
    }
    if (i < Nn) {
        int excl = ts[t] - v + g_boff[blockIdx.x];
        g_rp[i]  = excl;
        g_cur[i] = excl;
    }
    if (i == 0) g_rp[Nn] = Ee;
}

__global__ void fill_csr_kernel(const int* __restrict__ edge) {
    int e = blockIdx.x * blockDim.x + threadIdx.x;
    if (e < Ee) {
        int src = edge[e];
        int dst = edge[Ee + e];
        int p = atomicAdd(&g_cur[dst], 1);
        g_col[p] = src;
    }
}

// ---------------------------------------------------------------------------
// Aggregate: agg[i] = sum_{j in row i} xh[col[j]]  (fp16 hi gather, fp32 acc)
// One warp per row; each lane owns 4 columns (8 bytes of fp16 per neighbor).
// ---------------------------------------------------------------------------
__global__ void aggregate_kernel() {
    int w    = (blockIdx.x * blockDim.x + threadIdx.x) >> 5;
    int lane = threadIdx.x & 31;
    if (w >= Nn) return;
    int beg = g_rp[w];
    int end = g_rp[w + 1];
    float4 a0 = make_float4(0.f, 0.f, 0.f, 0.f);
    float4 a1 = make_float4(0.f, 0.f, 0.f, 0.f);
    int jb = beg;
    while (jb < end) {
        int take = min(32, end - jb);
        int myc = (lane < take) ? __ldg(&g_col[jb + lane]) : 0;
        int u = 0;
        for (; u + 1 < take; u += 2) {
            int s0 = __shfl_sync(0xffffffffu, myc, u);
            int s1 = __shfl_sync(0xffffffffu, myc, u + 1);
            __half2 p0 = *(const __half2*)(g_xh + (size_t)s0 * Dd + lane * 4);
            __half2 p1 = *(const __half2*)(g_xh + (size_t)s0 * Dd + lane * 4 + 2);
            __half2 q0 = *(const __half2*)(g_xh + (size_t)s1 * Dd + lane * 4);
            __half2 q1 = *(const __half2*)(g_xh + (size_t)s1 * Dd + lane * 4 + 2);
            float2 f0 = __half22float2(p0), f1 = __half22float2(p1);
            float2 e0 = __half22float2(q0), e1 = __half22float2(q1);
            a0.x += f0.x; a0.y += f0.y; a0.z += f1.x; a0.w += f1.y;
            a1.x += e0.x; a1.y += e0.y; a1.z += e1.x; a1.w += e1.y;
        }
        if (u < take) {
            int s0 = __shfl_sync(0xffffffffu, myc, u);
            __half2 p0 = *(const __half2*)(g_xh + (size_t)s0 * Dd + lane * 4);
            __half2 p1 = *(const __half2*)(g_xh + (size_t)s0 * Dd + lane * 4 + 2);
            float2 f0 = __half22float2(p0), f1 = __half22float2(p1);
            a0.x += f0.x; a0.y += f0.y; a0.z += f1.x; a0.w += f1.y;
        }
        jb += take;
    }
    float o0 = a0.x + a1.x, o1 = a0.y + a1.y;
    float o2 = a0.z + a1.z, o3 = a0.w + a1.w;
    size_t off = (size_t)w * Dd + lane * 4;
    __half h0, l0, h1, l1, h2, l2, h3, l3;
    split_h(o0, h0, l0); split_h(o1, h1, l1);
    split_h(o2, h2, l2); split_h(o3, h3, l3);
    *(__half2*)(g_aggh + off)     = __half2(h0, h1);
    *(__half2*)(g_aggh + off + 2) = __half2(h2, h3);
    *(__half2*)(g_aggl + off)     = __half2(l0, l1);
    *(__half2*)(g_aggl + off + 2) = __half2(l2, l3);
}

// ---------------------------------------------------------------------------
// mma.sync fp16-split dual-GEMM + bias + ReLU + residual + LayerNorm
//   acc = [agg|x] @ [Wl;Wr]  via 3-pass split fp16 (ah*bh + ah*bl + al*bh)
//   x_new = LN(relu(acc + bl) + x);  residual x reconstructed as hi+lo.
// CTA: 128x128 tile, 256 thr (8 warps, warp = 32x64). K=256 in 8 chunks of 32.
// smem: double-buffered {Ahi,Alo,Bhi,Blo}, rows of 40 half (conflict-free LDSM).
// ---------------------------------------------------------------------------
#define STR_H   40
#define TILE_HB (128 * STR_H * 2)          // 10240 B per tile
#define BUF_HB  (4 * TILE_HB)              // 40960 B per buffer
#define SMEM_MMA (2 * BUF_HB)              // 81920 B

__global__ void __launch_bounds__(256)
gemm_mma_kernel(int layer,
                const float* __restrict__ bias, const float* __restrict__ lng,
                const float* __restrict__ lnb, float* __restrict__ dout,
                int writeOut) {
    extern __shared__ char smem[];
    const uint32_t su = smem_u32(smem);
    const __half* bth = g_bth + (size_t)layer * 128 * 256;
    const __half* btl = g_btl + (size_t)layer * 128 * 256;
    const int t    = threadIdx.x;
    const int wid  = t >> 5;
    const int lane = t & 31;
    const int row0 = blockIdx.x * 128;
    const int mg   = wid & 3;         // m-group: rows mg*32..+31
    const int nh   = wid >> 2;        // n-half : cols nh*64..+63
    const int n0   = nh * 64;

    // staging assignment: rows sr, sr+64; 16B segment sg
    const int sr = t >> 2;
    const int sg = t & 3;

    float acc[64];                    // [mt][nt][4]
#pragma unroll
    for (int i = 0; i < 64; ++i) acc[i] = 0.f;

    auto stage = [&](int c) {
        const uint32_t bb = su + (c & 1) * BUF_HB;
        const __half* Ah = (c < 4) ? g_aggh : g_xh;
        const __half* Al = (c < 4) ? g_aggl : g_xl;
        const int ka = (c & 3) * 32;
#pragma unroll
        for (int rr = 0; rr < 2; ++rr) {
            const int r = sr + rr * 64;
            const int grow = row0 + r;
            const int ok = (grow < Nn);
            const size_t asrc = (size_t)(ok ? grow : 0) * Dd + ka + sg * 8;
            const uint32_t dofs = (uint32_t)(r * STR_H + sg * 8) * 2;
            cp16(bb + dofs,             Ah + asrc, ok);
            cp16(bb + TILE_HB + dofs,   Al + asrc, ok);
            const size_t bsrc = (size_t)r * 256 + c * 32 + sg * 8;
            cp16(bb + 2 * TILE_HB + dofs, bth + bsrc, 1);
            cp16(bb + 3 * TILE_HB + dofs, btl + bsrc, 1);
        }
        CP_COMMIT();
    };

    // ldmatrix lane-address components
    const int aRow = mg * 32 + (lane & 15);           // + mt*16
    const int aCol = (lane >> 4) * 8;                 // + kk
    const int bRow = n0 + (lane & 7) + ((lane >> 4) << 3);  // + g*16
    const int bCol = ((lane >> 3) & 1) * 8;           // + kk

    stage(0);
    CP_WAIT0();
    __syncthreads();

    for (int c = 0; c < 8; ++c) {
        const uint32_t bb = su + (c & 1) * BUF_HB;
        if (c < 7) stage(c + 1);
#pragma unroll
        for (int kk = 0; kk < 32; kk += 16) {
            uint32_t ah[2][4], al[2][4], bh[4][4], blo[4][4];
#pragma unroll
            for (int mt = 0; mt < 2; ++mt) {
                uint32_t ao = (uint32_t)((aRow + mt * 16) * STR_H + aCol + kk) * 2;
                ldsm4(ah[mt], bb + ao);
                ldsm4(al[mt], bb + TILE_HB + ao);
            }
#pragma unroll
            for (int g = 0; g < 4; ++g) {
                uint32_t bo = (uint32_t)((bRow + g * 16) * STR_H + bCol + kk) * 2;
                ldsm4(bh[g],  bb + 2 * TILE_HB + bo);
                ldsm4(blo[g], bb + 3 * TILE_HB + bo);
            }
#pragma unroll
            for (int mt = 0; mt < 2; ++mt)
#pragma unroll
                for (int g = 0; g < 4; ++g) {
                    float* d0 = &acc[(mt * 8 + 2 * g) * 4];
                    float* d1 = &acc[(mt * 8 + 2 * g + 1) * 4];
                    mma16816(d0, ah[mt], &bh[g][0]);
                    mma16816(d1, ah[mt], &bh[g][2]);
                    mma16816(d0, ah[mt], &blo[g][0]);
                    mma16816(d1, ah[mt], &blo[g][2]);
                    mma16816(d0, al[mt], &bh[g][0]);
                    mma16816(d1, al[mt], &bh[g][2]);
                }
        }
        if (c < 7) CP_WAIT0();
        __syncthreads();
    }

    // ------------------- Epilogue: bias+relu+residual+LN -------------------
    float* sred = (float*)smem;            // [128][8]
    float* qred = (float*)(smem + 4096);   // [128][8]

#pragma unroll
    for (int mt = 0; mt < 2; ++mt) {
        const int rl = mg * 32 + mt * 16 + (lane >> 2);
        const int rh = rl + 8;
        const int gl = row0 + rl, gh = row0 + rh;
        float sl = 0.f, ql = 0.f, sh = 0.f, qh = 0.f;
#pragma unroll
        for (int nt = 0; nt < 8; ++nt) {
            const int cc = n0 + nt * 8 + (lane & 3) * 2;
            float2 bi = *(const float2*)(bias + cc);
            float* a = &acc[(mt * 8 + nt) * 4];
            float h0 = fmaxf(a[0] + bi.x, 0.f);
            float h1 = fmaxf(a[1] + bi.y, 0.f);
            float h2 = fmaxf(a[2] + bi.x, 0.f);
            float h3 = fmaxf(a[3] + bi.y, 0.f);
            float2 xl2 = (gl < Nn) ? recon2(g_xh, g_xl, (size_t)gl * Dd + cc)
                                   : make_float2(0.f, 0.f);
            float2 xh2 = (gh < Nn) ? recon2(g_xh, g_xl, (size_t)gh * Dd + cc)
                                   : make_float2(0.f, 0.f);
            h0 += xl2.x; h1 += xl2.y; h2 += xh2.x; h3 += xh2.y;
            a[0] = h0; a[1] = h1; a[2] = h2; a[3] = h3;
            sl += h0 + h1; ql += h0 * h0 + h1 * h1;
            sh += h2 + h3; qh += h2 * h2 + h3 * h3;
        }
        sred[rl * 8 + nh * 4 + (lane & 3)] = sl;
        qred[rl * 8 + nh * 4 + (lane & 3)] = ql;
        sred[rh * 8 + nh * 4 + (lane & 3)] = sh;
        qred[rh * 8 + nh * 4 + (lane & 3)] = qh;
    }
    __syncthreads();

#pragma unroll
    for (int mt = 0; mt < 2; ++mt) {
        const int rl = mg * 32 + mt * 16 + (lane >> 2);
        const int rh = rl + 8;
        const int gl = row0 + rl, gh = row0 + rh;
        float s1 = 0.f, q1 = 0.f, s2 = 0.f, q2 = 0.f;
#pragma unroll
        for (int j = 0; j < 8; ++j) {
            s1 += sred[rl * 8 + j]; q1 += qred[rl * 8 + j];
            s2 += sred[rh * 8 + j]; q2 += qred[rh * 8 + j];
        }
        float m1 = s1 * (1.0f / 128.0f);
        float r1 = rsqrtf(q1 * (1.0f / 128.0f) - m1 * m1 + EPS_LN);
        float m2 = s2 * (1.0f / 128.0f);
        float r2 = rsqrtf(q2 * (1.0f / 128.0f) - m2 * m2 + EPS_LN);
#pragma unroll
        for (int nt = 0; nt < 8; ++nt) {
            const int cc = n0 + nt * 8 + (lane & 3) * 2;
            float2 gv = *(const float2*)(lng + cc);
            float2 tv = *(const float2*)(lnb + cc);
            float* a = &acc[(mt * 8 + nt) * 4];
            if (gl < Nn) {
                float o0 = (a[0] - m1) * r1 * gv.x + tv.x;
                float o1 = (a[1] - m1) * r1 * gv.y + tv.y;
                size_t off = (size_t)gl * Dd + cc;
                if (writeOut) {
                    *(float2*)(dout + off) = make_float2(o0, o1);
                } else {
                    __half hh0, ll0, hh1, ll1;
                    split_h(o0, hh0, ll0); split_h(o1, hh1, ll1);
                    *(__half2*)(g_xh + off) = __half2(hh0, hh1);
                    *(__half2*)(g_xl + off) = __half2(ll0, ll1);
                }
            }
            if (gh < Nn) {
                float o2 = (a[2] - m2) * r2 * gv.x + tv.x;
                float o3 = (a[3] - m2) * r2 * gv.y + tv.y;
                size_t off = (size_t)gh * Dd + cc;
                if (writeOut) {
                    *(float2*)(dout + off) = make_float2(o2, o3);
                } else {
                    __half hh2, ll2, hh3, ll3;
                    split_h(o2, hh2, ll2); split_h(o3, hh3, ll3);
                    *(__half2*)(g_xh + off) = __half2(hh2, hh3);
                    *(__half2*)(g_xl + off) = __half2(ll2, ll3);
                }
            }
        }
    }
}

// ---------------------------------------------------------------------------
extern "C" void kernel_launch(void* const* d_in, const int* in_sizes, int n_in,
                              void* d_out, int out_size) {
    const float* node_emb  = (const float*)d_in[0];
    const int*   pos       = (const int*)d_in[1];
    const int*   edge      = (const int*)d_in[2];
    const float* pos_table = (const float*)d_in[3];
    const float* Wl        = (const float*)d_in[4];
    const float* bl        = (const float*)d_in[5];
    const float* Wr        = (const float*)d_in[6];
    const float* emb_g     = (const float*)d_in[7];
    const float* emb_b     = (const float*)d_in[8];
    const float* hid_g     = (const float*)d_in[9];
    const float* hid_b     = (const float*)d_in[10];
    float* out = (float*)d_out;

    cudaFuncSetAttribute(gemm_mma_kernel,
                         cudaFuncAttributeMaxDynamicSharedMemorySize, SMEM_MMA);

    // embedding + LN (fp16 hi/lo splits only)
    embed_ln_kernel<<<(Nn * 32 + 255) / 256, 256>>>(node_emb, pos, pos_table,
                                                    emb_g, emb_b);
    // W^T hi/lo for all layers
    wt_kernel<<<(3 * 128 * 256 + 255) / 256, 256>>>(Wl, Wr);
    // CSR build (reused by all 3 layers)
    zero_deg_kernel<<<NBLK, 256>>>();
    hist_kernel<<<(Ee + 255) / 256, 256>>>(edge);
    deg_partials_kernel<<<NBLK, 256>>>();
    scan_partials_kernel<<<1, 256>>>();
    block_scan_kernel<<<NBLK, 256>>>();
    fill_csr_kernel<<<(Ee + 255) / 256, 256>>>(edge);

    const int gemm_blocks = (Nn + 127) / 128;  // 391
    for (int l = 0; l < 3; ++l) {
        aggregate_kernel<<<(Nn * 32 + 255) / 256, 256>>>();
        gemm_mma_kernel<<<gemm_blocks, 256, SMEM_MMA>>>(
            l, bl + (size_t)l * Dd, hid_g + (size_t)l * Dd,
            hid_b + (size_t)l * Dd, out, l == 2 ? 1 : 0);
    }
}

// round 10
// speedup vs baseline: 1.5224x; 1.0061x over previous
#include <cuda_runtime.h>
#include <cuda_fp16.h>
#include <cstdint>

#define Nn 50000
#define Dd 128
#define Ee 800000
#define EPS_LN 1e-5f
#define SQRT_D 11.313708498984761f
#define NBLK 196  // ceil(Nn/256)

// Scratch (static device globals — allocation-free per harness rules)
__device__ __half g_xh[Nn * Dd];     // fp16 hi split of x
__device__ __half g_xl[Nn * Dd];     // fp16 lo split of x
__device__ __half g_aggh[Nn * Dd];   // fp16 hi split of agg
__device__ __half g_aggl[Nn * Dd];   // fp16 lo split of agg
__device__ __half g_bth[3 * 128 * 256];  // W^T hi, [layer][n][k] (k<128:Wl, else Wr)
__device__ __half g_btl[3 * 128 * 256];  // W^T lo
__device__ int    g_deg[Nn];
__device__ int    g_rp[Nn + 1];
__device__ int    g_cur[Nn];
__device__ int    g_col[Ee];
__device__ int    g_part[NBLK];
__device__ int    g_boff[NBLK];

// ======================= PTX helpers ========================================
__device__ __forceinline__ uint32_t smem_u32(const void* p) {
    uint32_t a;
    asm("{ .reg .u64 t; cvta.to.shared.u64 t, %1; cvt.u32.u64 %0, t; }"
        : "=r"(a) : "l"(p));
    return a;
}
__device__ __forceinline__ void cp16(uint32_t dst, const void* src, int valid) {
    asm volatile("cp.async.ca.shared.global [%0], [%1], 16, %2;"
                 :: "r"(dst),
                    "l"((unsigned long long)__cvta_generic_to_global(src)),
                    "r"(valid ? 16 : 0));
}
#define CP_COMMIT() asm volatile("cp.async.commit_group;" ::: "memory")
#define CP_WAIT0()  asm volatile("cp.async.wait_group 0;" ::: "memory")

__device__ __forceinline__ void ldsm4(uint32_t* r, uint32_t addr) {
    asm volatile("ldmatrix.sync.aligned.m8n8.x4.shared.b16 {%0,%1,%2,%3}, [%4];"
                 : "=r"(r[0]), "=r"(r[1]), "=r"(r[2]), "=r"(r[3]) : "r"(addr));
}
__device__ __forceinline__ void mma16816(float* d, const uint32_t* a,
                                         const uint32_t* b) {
    asm volatile(
        "mma.sync.aligned.m16n8k16.row.col.f32.f16.f16.f32 "
        "{%0,%1,%2,%3}, {%4,%5,%6,%7}, {%8,%9}, {%0,%1,%2,%3};"
        : "+f"(d[0]), "+f"(d[1]), "+f"(d[2]), "+f"(d[3])
        : "r"(a[0]), "r"(a[1]), "r"(a[2]), "r"(a[3]), "r"(b[0]), "r"(b[1]));
}
__device__ __forceinline__ void split_h(float v, __half& hi, __half& lo) {
    hi = __float2half_rn(v);
    lo = __float2half_rn(v - __half2float(hi));
}
// reconstruct fp32 pair from hi/lo half2 arrays at (aligned) offset
__device__ __forceinline__ float2 recon2(const __half* hp, const __half* lp,
                                         size_t off) {
    float2 fh = __half22float2(*(const __half2*)(hp + off));
    float2 fl = __half22float2(*(const __half2*)(lp + off));
    return make_float2(fh.x + fl.x, fh.y + fl.y);
}
// accumulate a lane's 8-byte (4-half) slice of a row into 4 fp32 accumulators
__device__ __forceinline__ void acc_u2(uint2 v, float& a0, float& a1,
                                       float& a2, float& a3) {
    float2 f0 = __half22float2(*(const __half2*)&v.x);
    float2 f1 = __half22float2(*(const __half2*)&v.y);
    a0 += f0.x; a1 += f0.y; a2 += f1.x; a3 += f1.y;
}

// ---------------------------------------------------------------------------
// Kernel 1: x = LayerNorm(node_emb * sqrt(D) + pos_table[pos]); emit hi/lo.
// ---------------------------------------------------------------------------
__global__ void embed_ln_kernel(const float* __restrict__ ne,
                                const int* __restrict__ pos,
                                const float* __restrict__ ptab,
                                const float* __restrict__ g,
                                const float* __restrict__ b) {
    int w    = (blockIdx.x * blockDim.x + threadIdx.x) >> 5;
    int lane = threadIdx.x & 31;
    if (w >= Nn) return;
    int p = pos[w];
    float4 nv = *(const float4*)(ne   + (size_t)w * Dd + lane * 4);
    float4 pv = *(const float4*)(ptab + (size_t)p * Dd + lane * 4);
    float v0 = fmaf(nv.x, SQRT_D, pv.x);
    float v1 = fmaf(nv.y, SQRT_D, pv.y);
    float v2 = fmaf(nv.z, SQRT_D, pv.z);
    float v3 = fmaf(nv.w, SQRT_D, pv.w);
    float s = v0 + v1 + v2 + v3;
    float q = v0 * v0 + v1 * v1 + v2 * v2 + v3 * v3;
#pragma unroll
    for (int m = 1; m < 32; m <<= 1) {
        s += __shfl_xor_sync(0xffffffffu, s, m);
        q += __shfl_xor_sync(0xffffffffu, q, m);
    }
    float mean = s * (1.0f / 128.0f);
    float rstd = rsqrtf(q * (1.0f / 128.0f) - mean * mean + EPS_LN);
    float4 gv = *(const float4*)(g + lane * 4);
    float4 bv = *(const float4*)(b + lane * 4);
    float4 o;
    o.x = (v0 - mean) * rstd * gv.x + bv.x;
    o.y = (v1 - mean) * rstd * gv.y + bv.y;
    o.z = (v2 - mean) * rstd * gv.z + bv.z;
    o.w = (v3 - mean) * rstd * gv.w + bv.w;
    size_t off = (size_t)w * Dd + lane * 4;
    __half h0, l0, h1, l1, h2, l2, h3, l3;
    split_h(o.x, h0, l0); split_h(o.y, h1, l1);
    split_h(o.z, h2, l2); split_h(o.w, h3, l3);
    *(__half2*)(g_xh + off)     = __half2(h0, h1);
    *(__half2*)(g_xh + off + 2) = __half2(h2, h3);
    *(__half2*)(g_xl + off)     = __half2(l0, l1);
    *(__half2*)(g_xl + off + 2) = __half2(l2, l3);
}

// ---------------------------------------------------------------------------
// W^T hi/lo build: all 3 layers, bt[l][n][k] (k<128 -> Wl, else Wr)
// ---------------------------------------------------------------------------
__global__ void wt_kernel(const float* __restrict__ Wl,
                          const float* __restrict__ Wr) {
    int idx = blockIdx.x * blockDim.x + threadIdx.x;  // 3*128*256 = 98304
    if (idx >= 3 * 128 * 256) return;
    int l = idx >> 15;
    int r = idx & 32767;
    int n = r >> 8;
    int k = r & 255;
    float v = (k < 128) ? Wl[(size_t)l * Dd * Dd + k * Dd + n]
                        : Wr[(size_t)l * Dd * Dd + (k - 128) * Dd + n];
    __half hi, lo;
    split_h(v, hi, lo);
    g_bth[idx] = hi;
    g_btl[idx] = lo;
}

// ---------------------------------------------------------------------------
// CSR build: deg histogram -> 3-stage exclusive scan -> column fill
// ---------------------------------------------------------------------------
__global__ void zero_deg_kernel() {
    int i = blockIdx.x * blockDim.x + threadIdx.x;
    if (i < Nn) g_deg[i] = 0;
}

__global__ void hist_kernel(const int* __restrict__ edge) {
    int e = blockIdx.x * blockDim.x + threadIdx.x;
    if (e < Ee) atomicAdd(&g_deg[edge[Ee + e]], 1);
}

__global__ void deg_partials_kernel() {
    __shared__ int sm[256];
    int t = threadIdx.x;
    int i = blockIdx.x * 256 + t;
    int v = (i < Nn) ? g_deg[i] : 0;
    sm[t] = v;
    __syncthreads();
#pragma unroll
    for (int o = 128; o > 0; o >>= 1) {
        if (t < o) sm[t] += sm[t + o];
        __syncthreads();
    }
    if (t == 0) g_part[blockIdx.x] = sm[0];
}

__global__ void scan_partials_kernel() {
    __shared__ int ts[256];
    int t = threadIdx.x;
    int v = (t < NBLK) ? g_part[t] : 0;
    ts[t] = v;
    __syncthreads();
#pragma unroll
    for (int off = 1; off < 256; off <<= 1) {
        int u = (t >= off) ? ts[t - off] : 0;
        __syncthreads();
        ts[t] += u;
        __syncthreads();
    }
    if (t < NBLK) g_boff[t] = ts[t] - v;  // exclusive
}

__global__ void block_scan_kernel() {
    __shared__ int ts[256];
    int t = threadIdx.x;
    int i = blockIdx.x * 256 + t;
    int v = (i < Nn) ? g_deg[i] : 0;
    ts[t] = v;
    __syncthreads();
#pragma unroll
    for (int off = 1; off < 256; off <<= 1) {
        int u = (t >= off) ? ts[t - off] : 0;
        __syncthreads();
        ts[t] += u;
        __syncthreads();
    }
    if (i < Nn) {
        int excl = ts[t] - v + g_boff[blockIdx.x];
        g_rp[i]  = excl;
        g_cur[i] = excl;
    }
    if (i == 0) g_rp[Nn] = Ee;
}

__global__ void fill_csr_kernel(const int* __restrict__ edge) {
    int e = blockIdx.x * blockDim.x + threadIdx.x;
    if (e < Ee) {
        int src = edge[e];
        int dst = edge[Ee + e];
        int p = atomicAdd(&g_cur[dst], 1);
        g_col[p] = src;
    }
}

// ---------------------------------------------------------------------------
// Aggregate: agg[i] = sum_{j in row i} xh[col[j]]  (fp16 hi gather, fp32 acc)
// One warp per row; each lane owns 4 half columns = ONE uint2 LDG.64 per
// neighbor. Unrolled 4 neighbors deep for MLP=4.
// ---------------------------------------------------------------------------
__global__ void aggregate_kernel() {
    int w    = (blockIdx.x * blockDim.x + threadIdx.x) >> 5;
    int lane = threadIdx.x & 31;
    if (w >= Nn) return;
    int beg = g_rp[w];
    int end = g_rp[w + 1];
    const __half* xb = g_xh + lane * 4;
    float c0 = 0.f, c1 = 0.f, c2 = 0.f, c3 = 0.f;
    float d0 = 0.f, d1 = 0.f, d2 = 0.f, d3 = 0.f;
    int jb = beg;
    while (jb < end) {
        int take = min(32, end - jb);
        int myc = (lane < take) ? __ldg(&g_col[jb + lane]) : 0;
        int u = 0;
        for (; u + 3 < take; u += 4) {
            int s0 = __shfl_sync(0xffffffffu, myc, u);
            int s1 = __shfl_sync(0xffffffffu, myc, u + 1);
            int s2 = __shfl_sync(0xffffffffu, myc, u + 2);
            int s3 = __shfl_sync(0xffffffffu, myc, u + 3);
            uint2 v0 = *(const uint2*)(xb + (size_t)s0 * Dd);
            uint2 v1 = *(const uint2*)(xb + (size_t)s1 * Dd);
            uint2 v2 = *(const uint2*)(xb + (size_t)s2 * Dd);
            uint2 v3 = *(const uint2*)(xb + (size_t)s3 * Dd);
            acc_u2(v0, c0, c1, c2, c3);
            acc_u2(v1, d0, d1, d2, d3);
            acc_u2(v2, c0, c1, c2, c3);
            acc_u2(v3, d0, d1, d2, d3);
        }
        for (; u < take; ++u) {
            int s0 = __shfl_sync(0xffffffffu, myc, u);
            uint2 v0 = *(const uint2*)(xb + (size_t)s0 * Dd);
            acc_u2(v0, c0, c1, c2, c3);
        }
        jb += take;
    }
    float o0 = c0 + d0, o1 = c1 + d1, o2 = c2 + d2, o3 = c3 + d3;
    size_t off = (size_t)w * Dd + lane * 4;
    __half h0, l0, h1, l1, h2, l2, h3, l3;
    split_h(o0, h0, l0); split_h(o1, h1, l1);
    split_h(o2, h2, l2); split_h(o3, h3, l3);
    *(__half2*)(g_aggh + off)     = __half2(h0, h1);
    *(__half2*)(g_aggh + off + 2) = __half2(h2, h3);
    *(__half2*)(g_aggl + off)     = __half2(l0, l1);
    *(__half2*)(g_aggl + off + 2) = __half2(l2, l3);
}

// ---------------------------------------------------------------------------
// mma.sync fp16-split dual-GEMM + bias + ReLU + residual + LayerNorm
//   acc = [agg|x] @ [Wl;Wr]  via 3-pass split fp16 (ah*bh + ah*bl + al*bh)
//   x_new = LN(relu(acc + bl) + x);  residual x reconstructed as hi+lo.
// CTA: 128x128 tile, 256 thr (8 warps, warp = 32x64). K=256 in 8 chunks of 32.
// smem: double-buffered {Ahi,Alo,Bhi,Blo}, rows of 40 half (conflict-free LDSM).
// ---------------------------------------------------------------------------
#define STR_H   40
#define TILE_HB (128 * STR_H * 2)          // 10240 B per tile
#define BUF_HB  (4 * TILE_HB)              // 40960 B per buffer
#define SMEM_MMA (2 * BUF_HB)              // 81920 B

__global__ void __launch_bounds__(256)
gemm_mma_kernel(int layer,
                const float* __restrict__ bias, const float* __restrict__ lng,
                const float* __restrict__ lnb, float* __restrict__ dout,
                int writeOut) {
    extern __shared__ char smem[];
    const uint32_t su = smem_u32(smem);
    const __half* bth = g_bth + (size_t)layer * 128 * 256;
    const __half* btl = g_btl + (size_t)layer * 128 * 256;
    const int t    = threadIdx.x;
    const int wid  = t >> 5;
    const int lane = t & 31;
    const int row0 = blockIdx.x * 128;
    const int mg   = wid & 3;         // m-group: rows mg*32..+31
    const int nh   = wid >> 2;        // n-half : cols nh*64..+63
    const int n0   = nh * 64;

    // staging assignment: rows sr, sr+64; 16B segment sg
    const int sr = t >> 2;
    const int sg = t & 3;

    float acc[64];                    // [mt][nt][4]
#pragma unroll
    for (int i = 0; i < 64; ++i) acc[i] = 0.f;

    auto stage = [&](int c) {
        const uint32_t bb = su + (c & 1) * BUF_HB;
        const __half* Ah = (c < 4) ? g_aggh : g_xh;
        const __half* Al = (c < 4) ? g_aggl : g_xl;
        const int ka = (c & 3) * 32;
#pragma unroll
        for (int rr = 0; rr < 2; ++rr) {
            const int r = sr + rr * 64;
            const int grow = row0 + r;
            const int ok = (grow < Nn);
            const size_t asrc = (size_t)(ok ? grow : 0) * Dd + ka + sg * 8;
            const uint32_t dofs = (uint32_t)(r * STR_H + sg * 8) * 2;
            cp16(bb + dofs,             Ah + asrc, ok);
            cp16(bb + TILE_HB + dofs,   Al + asrc, ok);
            const size_t bsrc = (size_t)r * 256 + c * 32 + sg * 8;
            cp16(bb + 2 * TILE_HB + dofs, bth + bsrc, 1);
            cp16(bb + 3 * TILE_HB + dofs, btl + bsrc, 1);
        }
        CP_COMMIT();
    };

    // ldmatrix lane-address components
    const int aRow = mg * 32 + (lane & 15);           // + mt*16
    const int aCol = (lane >> 4) * 8;                 // + kk
    const int bRow = n0 + (lane & 7) + ((lane >> 4) << 3);  // + g*16
    const int bCol = ((lane >> 3) & 1) * 8;           // + kk

    stage(0);
    CP_WAIT0();
    __syncthreads();

    for (int c = 0; c < 8; ++c) {
        const uint32_t bb = su + (c & 1) * BUF_HB;
        if (c < 7) stage(c + 1);
#pragma unroll
        for (int kk = 0; kk < 32; kk += 16) {
            uint32_t ah[2][4], al[2][4], bh[4][4], blo[4][4];
#pragma unroll
            for (int mt = 0; mt < 2; ++mt) {
                uint32_t ao = (uint32_t)((aRow + mt * 16) * STR_H + aCol + kk) * 2;
                ldsm4(ah[mt], bb + ao);
                ldsm4(al[mt], bb + TILE_HB + ao);
            }
#pragma unroll
            for (int g = 0; g < 4; ++g) {
                uint32_t bo = (uint32_t)((bRow + g * 16) * STR_H + bCol + kk) * 2;
                ldsm4(bh[g],  bb + 2 * TILE_HB + bo);
                ldsm4(blo[g], bb + 3 * TILE_HB + bo);
            }
#pragma unroll
            for (int mt = 0; mt < 2; ++mt)
#pragma unroll
                for (int g = 0; g < 4; ++g) {
                    float* d0 = &acc[(mt * 8 + 2 * g) * 4];
                    float* d1 = &acc[(mt * 8 + 2 * g + 1) * 4];
                    mma16816(d0, ah[mt], &bh[g][0]);
                    mma16816(d1, ah[mt], &bh[g][2]);
                    mma16816(d0, ah[mt], &blo[g][0]);
                    mma16816(d1, ah[mt], &blo[g][2]);
                    mma16816(d0, al[mt], &bh[g][0]);
                    mma16816(d1, al[mt], &bh[g][2]);
                }
        }
        if (c < 7) CP_WAIT0();
        __syncthreads();
    }

    // ------------------- Epilogue: bias+relu+residual+LN -------------------
    float* sred = (float*)smem;            // [128][8]
    float* qred = (float*)(smem + 4096);   // [128][8]

#pragma unroll
    for (int mt = 0; mt < 2; ++mt) {
        const int rl = mg * 32 + mt * 16 + (lane >> 2);
        const int rh = rl + 8;
        const int gl = row0 + rl, gh = row0 + rh;
        float sl = 0.f, ql = 0.f, sh = 0.f, qh = 0.f;
#pragma unroll
        for (int nt = 0; nt < 8; ++nt) {
            const int cc = n0 + nt * 8 + (lane & 3) * 2;
            float2 bi = *(const float2*)(bias + cc);
            float* a = &acc[(mt * 8 + nt) * 4];
            float h0 = fmaxf(a[0] + bi.x, 0.f);
            float h1 = fmaxf(a[1] + bi.y, 0.f);
            float h2 = fmaxf(a[2] + bi.x, 0.f);
            float h3 = fmaxf(a[3] + bi.y, 0.f);
            float2 xl2 = (gl < Nn) ? recon2(g_xh, g_xl, (size_t)gl * Dd + cc)
                                   : make_float2(0.f, 0.f);
            float2 xh2 = (gh < Nn) ? recon2(g_xh, g_xl, (size_t)gh * Dd + cc)
                                   : make_float2(0.f, 0.f);
            h0 += xl2.x; h1 += xl2.y; h2 += xh2.x; h3 += xh2.y;
            a[0] = h0; a[1] = h1; a[2] = h2; a[3] = h3;
            sl += h0 + h1; ql += h0 * h0 + h1 * h1;
            sh += h2 + h3; qh += h2 * h2 + h3 * h3;
        }
        sred[rl * 8 + nh * 4 + (lane & 3)] = sl;
        qred[rl * 8 + nh * 4 + (lane & 3)] = ql;
        sred[rh * 8 + nh * 4 + (lane & 3)] = sh;
        qred[rh * 8 + nh * 4 + (lane & 3)] = qh;
    }
    __syncthreads();

#pragma unroll
    for (int mt = 0; mt < 2; ++mt) {
        const int rl = mg * 32 + mt * 16 + (lane >> 2);
        const int rh = rl + 8;
        const int gl = row0 + rl, gh = row0 + rh;
        float s1 = 0.f, q1 = 0.f, s2 = 0.f, q2 = 0.f;
#pragma unroll
        for (int j = 0; j < 8; ++j) {
            s1 += sred[rl * 8 + j]; q1 += qred[rl * 8 + j];
            s2 += sred[rh * 8 + j]; q2 += qred[rh * 8 + j];
        }
        float m1 = s1 * (1.0f / 128.0f);
        float r1 = rsqrtf(q1 * (1.0f / 128.0f) - m1 * m1 + EPS_LN);
        float m2 = s2 * (1.0f / 128.0f);
        float r2 = rsqrtf(q2 * (1.0f / 128.0f) - m2 * m2 + EPS_LN);
#pragma unroll
        for (int nt = 0; nt < 8; ++nt) {
            const int cc = n0 + nt * 8 + (lane & 3) * 2;
            float2 gv = *(const float2*)(lng + cc);
            float2 tv = *(const float2*)(lnb + cc);
            float* a = &acc[(mt * 8 + nt) * 4];
            if (gl < Nn) {
                float o0 = (a[0] - m1) * r1 * gv.x + tv.x;
                float o1 = (a[1] - m1) * r1 * gv.y + tv.y;
                size_t off = (size_t)gl * Dd + cc;
                if (writeOut) {
                    *(float2*)(dout + off) = make_float2(o0, o1);
                } else {
                    __half hh0, ll0, hh1, ll1;
                    split_h(o0, hh0, ll0); split_h(o1, hh1, ll1);
                    *(__half2*)(g_xh + off) = __half2(hh0, hh1);
                    *(__half2*)(g_xl + off) = __half2(ll0, ll1);
                }
            }
            if (gh < Nn) {
                float o2 = (a[2] - m2) * r2 * gv.x + tv.x;
                float o3 = (a[3] - m2) * r2 * gv.y + tv.y;
                size_t off = (size_t)gh * Dd + cc;
                if (writeOut) {
                    *(float2*)(dout + off) = make_float2(o2, o3);
                } else {
                    __half hh2, ll2, hh3, ll3;
                    split_h(o2, hh2, ll2); split_h(o3, hh3, ll3);
                    *(__half2*)(g_xh + off) = __half2(hh2, hh3);
                    *(__half2*)(g_xl + off) = __half2(ll2, ll3);
                }
            }
        }
    }
}

// ---------------------------------------------------------------------------
extern "C" void kernel_launch(void* const* d_in, const int* in_sizes, int n_in,
                              void* d_out, int out_size) {
    const float* node_emb  = (const float*)d_in[0];
    const int*   pos       = (const int*)d_in[1];
    const int*   edge      = (const int*)d_in[2];
    const float* pos_table = (const float*)d_in[3];
    const float* Wl        = (const float*)d_in[4];
    const float* bl        = (const float*)d_in[5];
    const float* Wr        = (const float*)d_in[6];
    const float* emb_g     = (const float*)d_in[7];
    const float* emb_b     = (const float*)d_in[8];
    const float* hid_g     = (const float*)d_in[9];
    const float* hid_b     = (const float*)d_in[10];
    float* out = (float*)d_out;

    cudaFuncSetAttribute(gemm_mma_kernel,
                         cudaFuncAttributeMaxDynamicSharedMemorySize, SMEM_MMA);

    // embedding + LN (fp16 hi/lo splits only)
    embed_ln_kernel<<<(Nn * 32 + 255) / 256, 256>>>(node_emb, pos, pos_table,
                                                    emb_g, emb_b);
    // W^T hi/lo for all layers
    wt_kernel<<<(3 * 128 * 256 + 255) / 256, 256>>>(Wl, Wr);
    // CSR build (reused by all 3 layers)
    zero_deg_kernel<<<NBLK, 256>>>();
    hist_kernel<<<(Ee + 255) / 256, 256>>>(edge);
    deg_partials_kernel<<<NBLK, 256>>>();
    scan_partials_kernel<<<1, 256>>>();
    block_scan_kernel<<<NBLK, 256>>>();
    fill_csr_kernel<<<(Ee + 255) / 256, 256>>>(edge);

    const int gemm_blocks = (Nn + 127) / 128;  // 391
    for (int l = 0; l < 3; ++l) {
        aggregate_kernel<<<(Nn * 32 + 255) / 256, 256>>>();
        gemm_mma_kernel<<<gemm_blocks, 256, SMEM_MMA>>>(
            l, bl + (size_t)l * Dd, hid_g + (size_t)l * Dd,
            hid_b + (size_t)l * Dd, out, l == 2 ? 1 : 0);
    }
}

// round 11
// speedup vs baseline: 1.7394x; 1.1425x over previous
#include <cuda_runtime.h>
#include <cuda_fp16.h>
#include <cstdint>

#define Nn 50000
#define Dd 128
#define Ee 800000
#define EPS_LN 1e-5f
#define SQRT_D 11.313708498984761f
#define NBLK 196  // ceil(Nn/256)

// Scratch (static device globals — allocation-free per harness rules)
__device__ __half g_xh[Nn * Dd];     // fp16 hi split of x
__device__ __half g_xl[Nn * Dd];     // fp16 lo split of x
__device__ __half g_aggh[Nn * Dd];   // fp16 hi split of agg
__device__ __half g_aggl[Nn * Dd];   // fp16 lo split of agg
__device__ __half g_bth[3 * 128 * 256];  // W^T hi, [layer][n][k] (k<128:Wl, else Wr)
__device__ int    g_deg[Nn];
__device__ int    g_rp[Nn + 1];
__device__ int    g_cur[Nn];
__device__ int    g_col[Ee];
__device__ int    g_part[NBLK];
__device__ int    g_boff[NBLK];

// ======================= PTX helpers ========================================
__device__ __forceinline__ uint32_t smem_u32(const void* p) {
    uint32_t a;
    asm("{ .reg .u64 t; cvta.to.shared.u64 t, %1; cvt.u32.u64 %0, t; }"
        : "=r"(a) : "l"(p));
    return a;
}
__device__ __forceinline__ void cp16(uint32_t dst, const void* src, int valid) {
    asm volatile("cp.async.ca.shared.global [%0], [%1], 16, %2;"
                 :: "r"(dst),
                    "l"((unsigned long long)__cvta_generic_to_global(src)),
                    "r"(valid ? 16 : 0));
}
#define CP_COMMIT() asm volatile("cp.async.commit_group;" ::: "memory")
#define CP_WAIT0()  asm volatile("cp.async.wait_group 0;" ::: "memory")

__device__ __forceinline__ void ldsm4(uint32_t* r, uint32_t addr) {
    asm volatile("ldmatrix.sync.aligned.m8n8.x4.shared.b16 {%0,%1,%2,%3}, [%4];"
                 : "=r"(r[0]), "=r"(r[1]), "=r"(r[2]), "=r"(r[3]) : "r"(addr));
}
__device__ __forceinline__ void mma16816(float* d, const uint32_t* a,
                                         const uint32_t* b) {
    asm volatile(
        "mma.sync.aligned.m16n8k16.row.col.f32.f16.f16.f32 "
        "{%0,%1,%2,%3}, {%4,%5,%6,%7}, {%8,%9}, {%0,%1,%2,%3};"
        : "+f"(d[0]), "+f"(d[1]), "+f"(d[2]), "+f"(d[3])
        : "r"(a[0]), "r"(a[1]), "r"(a[2]), "r"(a[3]), "r"(b[0]), "r"(b[1]));
}
__device__ __forceinline__ void split_h(float v, __half& hi, __half& lo) {
    hi = __float2half_rn(v);
    lo = __float2half_rn(v - __half2float(hi));
}
// reconstruct fp32 pair from hi/lo half2 arrays at (aligned) offset
__device__ __forceinline__ float2 recon2(const __half* hp, const __half* lp,
                                         size_t off) {
    float2 fh = __half22float2(*(const __half2*)(hp + off));
    float2 fl = __half22float2(*(const __half2*)(lp + off));
    return make_float2(fh.x + fl.x, fh.y + fl.y);
}
// accumulate a lane's 8-byte (4-half) slice of a row into 4 fp32 accumulators
__device__ __forceinline__ void acc_u2(uint2 v, float& a0, float& a1,
                                       float& a2, float& a3) {
    float2 f0 = __half22float2(*(const __half2*)&v.x);
    float2 f1 = __half22float2(*(const __half2*)&v.y);
    a0 += f0.x; a1 += f0.y; a2 += f1.x; a3 += f1.y;
}

// ---------------------------------------------------------------------------
// Kernel 1: x = LayerNorm(node_emb * sqrt(D) + pos_table[pos]); emit hi/lo.
// ---------------------------------------------------------------------------
__global__ void embed_ln_kernel(const float* __restrict__ ne,
                                const int* __restrict__ pos,
                                const float* __restrict__ ptab,
                                const float* __restrict__ g,
                                const float* __restrict__ b) {
    int w    = (blockIdx.x * blockDim.x + threadIdx.x) >> 5;
    int lane = threadIdx.x & 31;
    if (w >= Nn) return;
    int p = pos[w];
    float4 nv = *(const float4*)(ne   + (size_t)w * Dd + lane * 4);
    float4 pv = *(const float4*)(ptab + (size_t)p * Dd + lane * 4);
    float v0 = fmaf(nv.x, SQRT_D, pv.x);
    float v1 = fmaf(nv.y, SQRT_D, pv.y);
    float v2 = fmaf(nv.z, SQRT_D, pv.z);
    float v3 = fmaf(nv.w, SQRT_D, pv.w);
    float s = v0 + v1 + v2 + v3;
    float q = v0 * v0 + v1 * v1 + v2 * v2 + v3 * v3;
#pragma unroll
    for (int m = 1; m < 32; m <<= 1) {
        s += __shfl_xor_sync(0xffffffffu, s, m);
        q += __shfl_xor_sync(0xffffffffu, q, m);
    }
    float mean = s * (1.0f / 128.0f);
    float rstd = rsqrtf(q * (1.0f / 128.0f) - mean * mean + EPS_LN);
    float4 gv = *(const float4*)(g + lane * 4);
    float4 bv = *(const float4*)(b + lane * 4);
    float4 o;
    o.x = (v0 - mean) * rstd * gv.x + bv.x;
    o.y = (v1 - mean) * rstd * gv.y + bv.y;
    o.z = (v2 - mean) * rstd * gv.z + bv.z;
    o.w = (v3 - mean) * rstd * gv.w + bv.w;
    size_t off = (size_t)w * Dd + lane * 4;
    __half h0, l0, h1, l1, h2, l2, h3, l3;
    split_h(o.x, h0, l0); split_h(o.y, h1, l1);
    split_h(o.z, h2, l2); split_h(o.w, h3, l3);
    *(__half2*)(g_xh + off)     = __half2(h0, h1);
    *(__half2*)(g_xh + off + 2) = __half2(h2, h3);
    *(__half2*)(g_xl + off)     = __half2(l0, l1);
    *(__half2*)(g_xl + off + 2) = __half2(l2, l3);
}

// ---------------------------------------------------------------------------
// W^T hi build: all 3 layers, bt[l][n][k] (k<128 -> Wl, else Wr)
// (B-side lo term dropped: W fp16-RN noise ~2e-4 rel, within budget)
// ---------------------------------------------------------------------------
__global__ void wt_kernel(const float* __restrict__ Wl,
                          const float* __restrict__ Wr) {
    int idx = blockIdx.x * blockDim.x + threadIdx.x;  // 3*128*256 = 98304
    if (idx >= 3 * 128 * 256) return;
    int l = idx >> 15;
    int r = idx & 32767;
    int n = r >> 8;
    int k = r & 255;
    float v = (k < 128) ? Wl[(size_t)l * Dd * Dd + k * Dd + n]
                        : Wr[(size_t)l * Dd * Dd + (k - 128) * Dd + n];
    g_bth[idx] = __float2half_rn(v);
}

// ---------------------------------------------------------------------------
// CSR build: deg histogram -> 3-stage exclusive scan -> column fill
// ---------------------------------------------------------------------------
__global__ void zero_deg_kernel() {
    int i = blockIdx.x * blockDim.x + threadIdx.x;
    if (i < Nn) g_deg[i] = 0;
}

__global__ void hist_kernel(const int* __restrict__ edge) {
    int e = blockIdx.x * blockDim.x + threadIdx.x;
    if (e < Ee) atomicAdd(&g_deg[edge[Ee + e]], 1);
}

__global__ void deg_partials_kernel() {
    __shared__ int sm[256];
    int t = threadIdx.x;
    int i = blockIdx.x * 256 + t;
    int v = (i < Nn) ? g_deg[i] : 0;
    sm[t] = v;
    __syncthreads();
#pragma unroll
    for (int o = 128; o > 0; o >>= 1) {
        if (t < o) sm[t] += sm[t + o];
        __syncthreads();
    }
    if (t == 0) g_part[blockIdx.x] = sm[0];
}

__global__ void scan_partials_kernel() {
    __shared__ int ts[256];
    int t = threadIdx.x;
    int v = (t < NBLK) ? g_part[t] : 0;
    ts[t] = v;
    __syncthreads();
#pragma unroll
    for (int off = 1; off < 256; off <<= 1) {
        int u = (t >= off) ? ts[t - off] : 0;
        __syncthreads();
        ts[t] += u;
        __syncthreads();
    }
    if (t < NBLK) g_boff[t] = ts[t] - v;  // exclusive
}

__global__ void block_scan_kernel() {
    __shared__ int ts[256];
    int t = threadIdx.x;
    int i = blockIdx.x * 256 + t;
    int v = (i < Nn) ? g_deg[i] : 0;
    ts[t] = v;
    __syncthreads();
#pragma unroll
    for (int off = 1; off < 256; off <<= 1) {
        int u = (t >= off) ? ts[t - off] : 0;
        __syncthreads();
        ts[t] += u;
        __syncthreads();
    }
    if (i < Nn) {
        int excl = ts[t] - v + g_boff[blockIdx.x];
        g_rp[i]  = excl;
        g_cur[i] = excl;
    }
    if (i == 0) g_rp[Nn] = Ee;
}

__global__ void fill_csr_kernel(const int* __restrict__ edge) {
    int e = blockIdx.x * blockDim.x + threadIdx.x;
    if (e < Ee) {
        int src = edge[e];
        int dst = edge[Ee + e];
        int p = atomicAdd(&g_cur[dst], 1);
        g_col[p] = src;
    }
}

// ---------------------------------------------------------------------------
// Aggregate: agg[i] = sum_{j in row i} xh[col[j]]  (fp16 hi gather, fp32 acc)
// One warp per row; one uint2 LDG.64 per neighbor per lane, MLP=4 unroll.
// ---------------------------------------------------------------------------
__global__ void aggregate_kernel() {
    int w    = (blockIdx.x * blockDim.x + threadIdx.x) >> 5;
    int lane = threadIdx.x & 31;
    if (w >= Nn) return;
    int beg = g_rp[w];
    int end = g_rp[w + 1];
    const __half* xb = g_xh + lane * 4;
    float c0 = 0.f, c1 = 0.f, c2 = 0.f, c3 = 0.f;
    float d0 = 0.f, d1 = 0.f, d2 = 0.f, d3 = 0.f;
    int jb = beg;
    while (jb < end) {
        int take = min(32, end - jb);
        int myc = (lane < take) ? __ldg(&g_col[jb + lane]) : 0;
        int u = 0;
        for (; u + 3 < take; u += 4) {
            int s0 = __shfl_sync(0xffffffffu, myc, u);
            int s1 = __shfl_sync(0xffffffffu, myc, u + 1);
            int s2 = __shfl_sync(0xffffffffu, myc, u + 2);
            int s3 = __shfl_sync(0xffffffffu, myc, u + 3);
            uint2 v0 = *(const uint2*)(xb + (size_t)s0 * Dd);
            uint2 v1 = *(const uint2*)(xb + (size_t)s1 * Dd);
            uint2 v2 = *(const uint2*)(xb + (size_t)s2 * Dd);
            uint2 v3 = *(const uint2*)(xb + (size_t)s3 * Dd);
            acc_u2(v0, c0, c1, c2, c3);
            acc_u2(v1, d0, d1, d2, d3);
            acc_u2(v2, c0, c1, c2, c3);
            acc_u2(v3, d0, d1, d2, d3);
        }
        for (; u < take; ++u) {
            int s0 = __shfl_sync(0xffffffffu, myc, u);
            uint2 v0 = *(const uint2*)(xb + (size_t)s0 * Dd);
            acc_u2(v0, c0, c1, c2, c3);
        }
        jb += take;
    }
    float o0 = c0 + d0, o1 = c1 + d1, o2 = c2 + d2, o3 = c3 + d3;
    size_t off = (size_t)w * Dd + lane * 4;
    __half h0, l0, h1, l1, h2, l2, h3, l3;
    split_h(o0, h0, l0); split_h(o1, h1, l1);
    split_h(o2, h2, l2); split_h(o3, h3, l3);
    *(__half2*)(g_aggh + off)     = __half2(h0, h1);
    *(__half2*)(g_aggh + off + 2) = __half2(h2, h3);
    *(__half2*)(g_aggl + off)     = __half2(l0, l1);
    *(__half2*)(g_aggl + off + 2) = __half2(l2, l3);
}

// ---------------------------------------------------------------------------
// mma.sync fp16-split dual-GEMM + bias + ReLU + residual + LayerNorm
//   acc = [agg|x] @ [Wl;Wr]  via 2-pass split fp16 (ah*bh + al*bh)
//   x_new = LN(relu(acc + bl) + x);  residual x reconstructed as hi+lo.
// CTA: 128x128 tile, 256 thr (8 warps, warp = 32x64). K=256 in 8 chunks of 32.
// smem: double-buffered {Ahi,Alo,Bhi}, rows of 40 half (conflict-free LDSM).
// ---------------------------------------------------------------------------
#define STR_H   40
#define TILE_HB (128 * STR_H * 2)          // 10240 B per tile
#define BUF_HB  (3 * TILE_HB)              // 30720 B per buffer
#define SMEM_MMA (2 * BUF_HB)              // 61440 B

__global__ void __launch_bounds__(256)
gemm_mma_kernel(int layer,
                const float* __restrict__ bias, const float* __restrict__ lng,
                const float* __restrict__ lnb, float* __restrict__ dout,
                int writeOut) {
    extern __shared__ char smem[];
    const uint32_t su = smem_u32(smem);
    const __half* bth = g_bth + (size_t)layer * 128 * 256;
    const int t    = threadIdx.x;
    const int wid  = t >> 5;
    const int lane = t & 31;
    const int row0 = blockIdx.x * 128;
    const int mg   = wid & 3;         // m-group: rows mg*32..+31
    const int nh   = wid >> 2;        // n-half : cols nh*64..+63
    const int n0   = nh * 64;

    // staging assignment: rows sr, sr+64; 16B segment sg
    const int sr = t >> 2;
    const int sg = t & 3;

    float acc[64];                    // [mt][nt][4]
#pragma unroll
    for (int i = 0; i < 64; ++i) acc[i] = 0.f;

    auto stage = [&](int c) {
        const uint32_t bb = su + (c & 1) * BUF_HB;
        const __half* Ah = (c < 4) ? g_aggh : g_xh;
        const __half* Al = (c < 4) ? g_aggl : g_xl;
        const int ka = (c & 3) * 32;
#pragma unroll
        for (int rr = 0; rr < 2; ++rr) {
            const int r = sr + rr * 64;
            const int grow = row0 + r;
            const int ok = (grow < Nn);
            const size_t asrc = (size_t)(ok ? grow : 0) * Dd + ka + sg * 8;
            const uint32_t dofs = (uint32_t)(r * STR_H + sg * 8) * 2;
            cp16(bb + dofs,             Ah + asrc, ok);
            cp16(bb + TILE_HB + dofs,   Al + asrc, ok);
            const size_t bsrc = (size_t)r * 256 + c * 32 + sg * 8;
            cp16(bb + 2 * TILE_HB + dofs, bth + bsrc, 1);
        }
        CP_COMMIT();
    };

    // ldmatrix lane-address components
    const int aRow = mg * 32 + (lane & 15);           // + mt*16
    const int aCol = (lane >> 4) * 8;                 // + kk
    const int bRow = n0 + (lane & 7) + ((lane >> 4) << 3);  // + g*16
    const int bCol = ((lane >> 3) & 1) * 8;           // + kk

    stage(0);
    CP_WAIT0();
    __syncthreads();

    for (int c = 0; c < 8; ++c) {
        const uint32_t bb = su + (c & 1) * BUF_HB;
        if (c < 7) stage(c + 1);
#pragma unroll
        for (int kk = 0; kk < 32; kk += 16) {
            uint32_t ah[2][4], al[2][4], bh[4][4];
#pragma unroll
            for (int mt = 0; mt < 2; ++mt) {
                uint32_t ao = (uint32_t)((aRow + mt * 16) * STR_H + aCol + kk) * 2;
                ldsm4(ah[mt], bb + ao);
                ldsm4(al[mt], bb + TILE_HB + ao);
            }
#pragma unroll
            for (int g = 0; g < 4; ++g) {
                uint32_t bo = (uint32_t)((bRow + g * 16) * STR_H + bCol + kk) * 2;
                ldsm4(bh[g], bb + 2 * TILE_HB + bo);
            }
#pragma unroll
            for (int mt = 0; mt < 2; ++mt)
#pragma unroll
                for (int g = 0; g < 4; ++g) {
                    float* d0 = &acc[(mt * 8 + 2 * g) * 4];
                    float* d1 = &acc[(mt * 8 + 2 * g + 1) * 4];
                    mma16816(d0, ah[mt], &bh[g][0]);
                    mma16816(d1, ah[mt], &bh[g][2]);
                    mma16816(d0, al[mt], &bh[g][0]);
                    mma16816(d1, al[mt], &bh[g][2]);
                }
        }
        if (c < 7) CP_WAIT0();
        __syncthreads();
    }

    // ------------------- Epilogue: bias+relu+residual+LN -------------------
    float* sred = (float*)smem;            // [128][8]
    float* qred = (float*)(smem + 4096);   // [128][8]

#pragma unroll
    for (int mt = 0; mt < 2; ++mt) {
        const int rl = mg * 32 + mt * 16 + (lane >> 2);
        const int rh = rl + 8;
        const int gl = row0 + rl, gh = row0 + rh;
        float sl = 0.f, ql = 0.f, sh = 0.f, qh = 0.f;
#pragma unroll
        for (int nt = 0; nt < 8; ++nt) {
            const int cc = n0 + nt * 8 + (lane & 3) * 2;
            float2 bi = *(const float2*)(bias + cc);
            float* a = &acc[(mt * 8 + nt) * 4];
            float h0 = fmaxf(a[0] + bi.x, 0.f);
            float h1 = fmaxf(a[1] + bi.y, 0.f);
            float h2 = fmaxf(a[2] + bi.x, 0.f);
            float h3 = fmaxf(a[3] + bi.y, 0.f);
            float2 xl2 = (gl < Nn) ? recon2(g_xh, g_xl, (size_t)gl * Dd + cc)
                                   : make_float2(0.f, 0.f);
            float2 xh2 = (gh < Nn) ? recon2(g_xh, g_xl, (size_t)gh * Dd + cc)
                                   : make_float2(0.f, 0.f);
            h0 += xl2.x; h1 += xl2.y; h2 += xh2.x; h3 += xh2.y;
            a[0] = h0; a[1] = h1; a[2] = h2; a[3] = h3;
            sl += h0 + h1; ql += h0 * h0 + h1 * h1;
            sh += h2 + h3; qh += h2 * h2 + h3 * h3;
        }
        sred[rl * 8 + nh * 4 + (lane & 3)] = sl;
        qred[rl * 8 + nh * 4 + (lane & 3)] = ql;
        sred[rh * 8 + nh * 4 + (lane & 3)] = sh;
        qred[rh * 8 + nh * 4 + (lane & 3)] = qh;
    }
    __syncthreads();

#pragma unroll
    for (int mt = 0; mt < 2; ++mt) {
        const int rl = mg * 32 + mt * 16 + (lane >> 2);
        const int rh = rl + 8;
        const int gl = row0 + rl, gh = row0 + rh;
        float s1 = 0.f, q1 = 0.f, s2 = 0.f, q2 = 0.f;
#pragma unroll
        for (int j = 0; j < 8; ++j) {
            s1 += sred[rl * 8 + j]; q1 += qred[rl * 8 + j];
            s2 += sred[rh * 8 + j]; q2 += qred[rh * 8 + j];
        }
        float m1 = s1 * (1.0f / 128.0f);
        float r1 = rsqrtf(q1 * (1.0f / 128.0f) - m1 * m1 + EPS_LN);
        float m2 = s2 * (1.0f / 128.0f);
        float r2 = rsqrtf(q2 * (1.0f / 128.0f) - m2 * m2 + EPS_LN);
#pragma unroll
        for (int nt = 0; nt < 8; ++nt) {
            const int cc = n0 + nt * 8 + (lane & 3) * 2;
            float2 gv = *(const float2*)(lng + cc);
            float2 tv = *(const float2*)(lnb + cc);
            float* a = &acc[(mt * 8 + nt) * 4];
            if (gl < Nn) {
                float o0 = (a[0] - m1) * r1 * gv.x + tv.x;
                float o1 = (a[1] - m1) * r1 * gv.y + tv.y;
                size_t off = (size_t)gl * Dd + cc;
                if (writeOut) {
                    *(float2*)(dout + off) = make_float2(o0, o1);
                } else {
                    __half hh0, ll0, hh1, ll1;
                    split_h(o0, hh0, ll0); split_h(o1, hh1, ll1);
                    *(__half2*)(g_xh + off) = __half2(hh0, hh1);
                    *(__half2*)(g_xl + off) = __half2(ll0, ll1);
                }
            }
            if (gh < Nn) {
                float o2 = (a[2] - m2) * r2 * gv.x + tv.x;
                float o3 = (a[3] - m2) * r2 * gv.y + tv.y;
                size_t off = (size_t)gh * Dd + cc;
                if (writeOut) {
                    *(float2*)(dout + off) = make_float2(o2, o3);
                } else {
                    __half hh2, ll2, hh3, ll3;
                    split_h(o2, hh2, ll2); split_h(o3, hh3, ll3);
                    *(__half2*)(g_xh + off) = __half2(hh2, hh3);
                    *(__half2*)(g_xl + off) = __half2(ll2, ll3);
                }
            }
        }
    }
}

// ---------------------------------------------------------------------------
extern "C" void kernel_launch(void* const* d_in, const int* in_sizes, int n_in,
                              void* d_out, int out_size) {
    const float* node_emb  = (const float*)d_in[0];
    const int*   pos       = (const int*)d_in[1];
    const int*   edge      = (const int*)d_in[2];
    const float* pos_table = (const float*)d_in[3];
    const float* Wl        = (const float*)d_in[4];
    const float* bl        = (const float*)d_in[5];
    const float* Wr        = (const float*)d_in[6];
    const float* emb_g     = (const float*)d_in[7];
    const float* emb_b     = (const float*)d_in[8];
    const float* hid_g     = (const float*)d_in[9];
    const float* hid_b     = (const float*)d_in[10];
    float* out = (float*)d_out;

    cudaFuncSetAttribute(gemm_mma_kernel,
                         cudaFuncAttributeMaxDynamicSharedMemorySize, SMEM_MMA);

    // embedding + LN (fp16 hi/lo splits only)
    embed_ln_kernel<<<(Nn * 32 + 255) / 256, 256>>>(node_emb, pos, pos_table,
                                                    emb_g, emb_b);
    // W^T hi for all layers
    wt_kernel<<<(3 * 128 * 256 + 255) / 256, 256>>>(Wl, Wr);
    // CSR build (reused by all 3 layers)
    zero_deg_kernel<<<NBLK, 256>>>();
    hist_kernel<<<(Ee + 255) / 256, 256>>>(edge);
    deg_partials_kernel<<<NBLK, 256>>>();
    scan_partials_kernel<<<1, 256>>>();
    block_scan_kernel<<<NBLK, 256>>>();
    fill_csr_kernel<<<(Ee + 255) / 256, 256>>>(edge);

    const int gemm_blocks = (Nn + 127) / 128;  // 391
    for (int l = 0; l < 3; ++l) {
        aggregate_kernel<<<(Nn * 32 + 255) / 256, 256>>>();
        gemm_mma_kernel<<<gemm_blocks, 256, SMEM_MMA>>>(
            l, bl + (size_t)l * Dd, hid_g + (size_t)l * Dd,
            hid_b + (size_t)l * Dd, out, l == 2 ? 1 : 0);
    }
}